// round 2
// baseline (speedup 1.0000x reference)
#include <cuda_runtime.h>
#include <math.h>

#define BATCH 4
#define SEQ   2048
#define CDIM  384
#define NH    6
#define HD    64

// Scratch (static __device__ arrays — no runtime allocation allowed).
__device__ float g_q[BATCH*NH*SEQ*HD];
__device__ float g_k[BATCH*NH*SEQ*HD];
__device__ float g_v[BATCH*NH*SEQ*HD];
__device__ float g_y[BATCH*NH*SEQ*HD];

// ---------------------------------------------------------------------------
// GEMM: out[r, j] = sum_c A[r, c] * W[j, c]
//   SRC 0: A = x [B*T, C] row-major        SRC 1: gather from g_y [B,H,T,D]
//   DST 0/1/2: g_q/g_k/g_v as [B,H,T,D] (blockIdx.y = head)
//   DST 3: outp as [B,T,C]
//   ROPE: apply RoPE + RMSNorm to the 64-wide head vector in the epilogue.
// Tiling: 64(M) x 64(N) x 32(K) per block, 256 threads, 4x4 micro-tile.
// ---------------------------------------------------------------------------
template<int SRC, int DST, bool ROPE>
__global__ __launch_bounds__(256)
void gemm_kernel(const float* __restrict__ A,
                 const float* __restrict__ W,
                 const float* __restrict__ cosp,
                 const float* __restrict__ sinp,
                 float* __restrict__ outp)
{
    __shared__ float As[32][65];   // As[k][t]  (pad 1 -> conflict-free store)
    __shared__ float Bs[32][65];   // Bs[k][j]

    const int tid = threadIdx.x;
    const int tx  = tid & 15;
    const int ty  = tid >> 4;
    const int rbase = blockIdx.x * 64;
    const int jb    = blockIdx.y * 64;

    float acc[4][4];
    #pragma unroll
    for (int i = 0; i < 4; i++)
        #pragma unroll
        for (int j = 0; j < 4; j++) acc[i][j] = 0.0f;

    const int lc = tid & 31;   // k within tile
    const int lr = tid >> 5;   // row group 0..7

    for (int kb = 0; kb < CDIM; kb += 32) {
        #pragma unroll
        for (int it = 0; it < 8; it++) {
            int rl = lr + it * 8;
            int r  = rbase + rl;
            float av;
            if (SRC == 1) {
                int bb = r >> 11, t = r & (SEQ - 1);
                int cc = kb + lc;
                av = g_y[((size_t)(bb * NH + (cc >> 6)) * SEQ + t) * HD + (cc & 63)];
            } else {
                av = A[(size_t)r * CDIM + kb + lc];
            }
            As[lc][rl] = av;
            Bs[lc][rl] = W[(size_t)(jb + rl) * CDIM + kb + lc];
        }
        __syncthreads();
        #pragma unroll
        for (int k = 0; k < 32; k++) {
            float a0 = As[k][ty], a1 = As[k][ty + 16], a2 = As[k][ty + 32], a3 = As[k][ty + 48];
            float b0 = Bs[k][tx], b1 = Bs[k][tx + 16], b2 = Bs[k][tx + 32], b3 = Bs[k][tx + 48];
            acc[0][0] += a0 * b0; acc[0][1] += a0 * b1; acc[0][2] += a0 * b2; acc[0][3] += a0 * b3;
            acc[1][0] += a1 * b0; acc[1][1] += a1 * b1; acc[1][2] += a1 * b2; acc[1][3] += a1 * b3;
            acc[2][0] += a2 * b0; acc[2][1] += a2 * b1; acc[2][2] += a2 * b2; acc[2][3] += a2 * b3;
            acc[3][0] += a3 * b0; acc[3][1] += a3 * b1; acc[3][2] += a3 * b2; acc[3][3] += a3 * b3;
        }
        __syncthreads();
    }

    // Epilogue. Thread holds rows (ty + 16*i), cols (tx + 16*ii).
    // For ROPE: cols jb..jb+63 are exactly one head. Pairs (d, d+32) = (v0,v2),(v1,v3).
    #pragma unroll
    for (int i = 0; i < 4; i++) {
        int r = rbase + ty + 16 * i;
        float v0 = acc[i][0], v1 = acc[i][1], v2 = acc[i][2], v3 = acc[i][3];
        if (ROPE) {
            int t = r & (SEQ - 1);
            float c0 = cosp[t * 32 + tx],      s0 = sinp[t * 32 + tx];
            float c1 = cosp[t * 32 + tx + 16], s1 = sinp[t * 32 + tx + 16];
            float n0 =  v0 * c0 + v2 * s0;
            float n2 = -v0 * s0 + v2 * c0;
            float n1 =  v1 * c1 + v3 * s1;
            float n3 = -v1 * s1 + v3 * c1;
            float ss = n0 * n0 + n1 * n1 + n2 * n2 + n3 * n3;
            // row lives across the 16 tx lanes of this half-warp
            ss += __shfl_xor_sync(0xffffffffu, ss, 1);
            ss += __shfl_xor_sync(0xffffffffu, ss, 2);
            ss += __shfl_xor_sync(0xffffffffu, ss, 4);
            ss += __shfl_xor_sync(0xffffffffu, ss, 8);
            float rn = rsqrtf(ss * (1.0f / HD) + 1.1920929e-07f);
            v0 = n0 * rn; v1 = n1 * rn; v2 = n2 * rn; v3 = n3 * rn;
        }
        if (DST == 3) {
            float* o = outp + (size_t)r * CDIM + jb;
            o[tx] = v0; o[tx + 16] = v1; o[tx + 32] = v2; o[tx + 48] = v3;
        } else {
            float* base = (DST == 0) ? g_q : (DST == 1) ? g_k : g_v;
            int bb = r >> 11, t = r & (SEQ - 1);
            float* o = base + ((size_t)(bb * NH + blockIdx.y) * SEQ + t) * HD;
            o[tx] = v0; o[tx + 16] = v1; o[tx + 32] = v2; o[tx + 48] = v3;
        }
    }
}

// ---------------------------------------------------------------------------
// Flash attention, fp32, online softmax. All smem tiles row-major [64][64]
// with 16B-granule XOR swizzle: granule g of row r stored at g ^ ((r>>2)&15).
// Conflict-free LDS.128/STS.128 everywhere.
// Threads: 256 as 16(cy) x 16(cx). Thread owns rows cy*4..+3, cols cx*4..+3.
// ---------------------------------------------------------------------------
__global__ __launch_bounds__(256)
void attn_kernel(const int* __restrict__ tmask,
                 const float* __restrict__ mb_raw,
                 const int* __restrict__ bsp)
{
    __shared__ __align__(16) float Qs[64 * 64];
    __shared__ __align__(16) float Ks[64 * 64];   // reused as P after scores
    __shared__ __align__(16) float Vs[64 * 64];
    float* Ps = Ks;

    const int tid = threadIdx.x;
    const int cx  = tid & 15;
    const int cy  = tid >> 4;
    const int bh  = blockIdx.y;          // b*NH + h
    const int b   = bh / NH;
    const int h   = bh - b * NH;
    const int qb  = blockIdx.x * 64;

    const float* Qg = g_q + (size_t)bh * SEQ * HD;
    const float* Kg = g_k + (size_t)bh * SEQ * HD;
    const float* Vg = g_v + (size_t)bh * SEQ * HD;
    float*       Yg = g_y + (size_t)bh * SEQ * HD;

    // bias_scale: handle either int32 or float32 payload robustly.
    float bs;
    {
        int iv = bsp[0];
        bs = (iv > -1000000 && iv < 1000000) ? (float)iv : __int_as_float(iv);
    }
    float t0 = tanhf(mb_raw[h * 3 + 0]);
    float t1 = tanhf(mb_raw[h * 3 + 1]);
    float t2 = tanhf(mb_raw[h * 3 + 2]);
    float G1 = 0.5f * t0 * bs, G2 = 0.5f * t1 * bs, G3 = 0.5f * t2 * bs;
    float b01 = fminf(2.0f, fmaxf(-2.0f, G2));            // mi=0, mj=1
    float b10 = fminf(2.0f, fmaxf(-2.0f, G1));            // mi=1, mj=0
    float b11 = fminf(2.0f, fmaxf(-2.0f, G1 + G2 + G3));  // mi=1, mj=1

    // Load Q tile (swizzled row-major).
    #pragma unroll
    for (int it = 0; it < 4; it++) {
        int idx = tid + it * 256;
        int r = idx >> 4, g = idx & 15;
        float4 qv = *(const float4*)(Qg + (size_t)(qb + r) * HD + g * 4);
        *(float4*)(Qs + r * 64 + ((g ^ (r >> 2)) << 2)) = qv;
    }

    int mi[4];
    #pragma unroll
    for (int rr = 0; rr < 4; rr++) mi[rr] = tmask[b * SEQ + qb + cy * 4 + rr];

    float  m[4], l[4];
    float4 o[4];
    #pragma unroll
    for (int rr = 0; rr < 4; rr++) {
        m[rr] = -1e30f; l[rr] = 0.0f;
        o[rr] = make_float4(0.f, 0.f, 0.f, 0.f);
    }

    for (int kt = 0; kt < SEQ / 64; kt++) {
        __syncthreads();   // previous P/V reads complete before overwrite
        #pragma unroll
        for (int it = 0; it < 4; it++) {
            int idx = tid + it * 256;
            int r = idx >> 4, g = idx & 15;
            const float* kp = Kg + (size_t)(kt * 64 + r) * HD + g * 4;
            const float* vp = Vg + (size_t)(kt * 64 + r) * HD + g * 4;
            float4 kv = *(const float4*)kp;
            float4 vv = *(const float4*)vp;
            int sg = ((g ^ (r >> 2)) << 2);
            *(float4*)(Ks + r * 64 + sg) = kv;
            *(float4*)(Vs + r * 64 + sg) = vv;
        }
        __syncthreads();

        // ---- scores: s4[rr] = q(row) . k(col group) ----
        float4 s4[4];
        #pragma unroll
        for (int rr = 0; rr < 4; rr++) s4[rr] = make_float4(0.f, 0.f, 0.f, 0.f);

        #pragma unroll 4
        for (int g = 0; g < 16; g++) {
            int kg = ((g ^ cx) << 2);
            float4 k0 = *(const float4*)(Ks + (cx * 4 + 0) * 64 + kg);
            float4 k1 = *(const float4*)(Ks + (cx * 4 + 1) * 64 + kg);
            float4 k2 = *(const float4*)(Ks + (cx * 4 + 2) * 64 + kg);
            float4 k3 = *(const float4*)(Ks + (cx * 4 + 3) * 64 + kg);
            int qg = ((g ^ cy) << 2);
            #pragma unroll
            for (int rr = 0; rr < 4; rr++) {
                float4 q = *(const float4*)(Qs + (cy * 4 + rr) * 64 + qg);
                s4[rr].x += q.x * k0.x + q.y * k0.y + q.z * k0.z + q.w * k0.w;
                s4[rr].y += q.x * k1.x + q.y * k1.y + q.z * k1.z + q.w * k1.w;
                s4[rr].z += q.x * k2.x + q.y * k2.y + q.z * k2.z + q.w * k2.w;
                s4[rr].w += q.x * k3.x + q.y * k3.y + q.z * k3.z + q.w * k3.w;
            }
        }

        // ---- bias + online softmax ----
        const int* mjp = tmask + b * SEQ + kt * 64 + cx * 4;
        int mj0 = mjp[0], mj1 = mjp[1], mj2 = mjp[2], mj3 = mjp[3];
        float c00 = mj0 ? b01 : 0.f, c10 = mj0 ? b11 : b10;
        float c01 = mj1 ? b01 : 0.f, c11 = mj1 ? b11 : b10;
        float c02 = mj2 ? b01 : 0.f, c12 = mj2 ? b11 : b10;
        float c03 = mj3 ? b01 : 0.f, c13 = mj3 ? b11 : b10;

        #pragma unroll
        for (int rr = 0; rr < 4; rr++) {
            float e0 = mi[rr] ? c10 : c00;
            float e1 = mi[rr] ? c11 : c01;
            float e2 = mi[rr] ? c12 : c02;
            float e3 = mi[rr] ? c13 : c03;
            s4[rr].x = s4[rr].x * 0.125f + e0;
            s4[rr].y = s4[rr].y * 0.125f + e1;
            s4[rr].z = s4[rr].z * 0.125f + e2;
            s4[rr].w = s4[rr].w * 0.125f + e3;

            float mx = fmaxf(fmaxf(s4[rr].x, s4[rr].y), fmaxf(s4[rr].z, s4[rr].w));
            mx = fmaxf(mx, __shfl_xor_sync(0xffffffffu, mx, 1));
            mx = fmaxf(mx, __shfl_xor_sync(0xffffffffu, mx, 2));
            mx = fmaxf(mx, __shfl_xor_sync(0xffffffffu, mx, 4));
            mx = fmaxf(mx, __shfl_xor_sync(0xffffffffu, mx, 8));

            float mn = fmaxf(m[rr], mx);
            float a  = __expf(m[rr] - mn);
            s4[rr].x = __expf(s4[rr].x - mn);
            s4[rr].y = __expf(s4[rr].y - mn);
            s4[rr].z = __expf(s4[rr].z - mn);
            s4[rr].w = __expf(s4[rr].w - mn);
            float ps = s4[rr].x + s4[rr].y + s4[rr].z + s4[rr].w;
            ps += __shfl_xor_sync(0xffffffffu, ps, 1);
            ps += __shfl_xor_sync(0xffffffffu, ps, 2);
            ps += __shfl_xor_sync(0xffffffffu, ps, 4);
            ps += __shfl_xor_sync(0xffffffffu, ps, 8);
            l[rr] = l[rr] * a + ps;
            m[rr] = mn;
            o[rr].x *= a; o[rr].y *= a; o[rr].z *= a; o[rr].w *= a;
        }

        // ---- stash P (overwrites Ks) ----
        __syncthreads();
        #pragma unroll
        for (int rr = 0; rr < 4; rr++) {
            int r = cy * 4 + rr;
            *(float4*)(Ps + r * 64 + ((cx ^ cy) << 2)) = s4[rr];
        }
        __syncthreads();

        // ---- o += P @ V ----
        #pragma unroll 4
        for (int g = 0; g < 16; g++) {
            float4 p0 = *(const float4*)(Ps + (cy * 4 + 0) * 64 + ((g ^ cy) << 2));
            float4 p1 = *(const float4*)(Ps + (cy * 4 + 1) * 64 + ((g ^ cy) << 2));
            float4 p2 = *(const float4*)(Ps + (cy * 4 + 2) * 64 + ((g ^ cy) << 2));
            float4 p3 = *(const float4*)(Ps + (cy * 4 + 3) * 64 + ((g ^ cy) << 2));
            int vg = ((cx ^ g) << 2);
            float4 v0 = *(const float4*)(Vs + (g * 4 + 0) * 64 + vg);
            float4 v1 = *(const float4*)(Vs + (g * 4 + 1) * 64 + vg);
            float4 v2 = *(const float4*)(Vs + (g * 4 + 2) * 64 + vg);
            float4 v3 = *(const float4*)(Vs + (g * 4 + 3) * 64 + vg);

            o[0].x += p0.x*v0.x + p0.y*v1.x + p0.z*v2.x + p0.w*v3.x;
            o[0].y += p0.x*v0.y + p0.y*v1.y + p0.z*v2.y + p0.w*v3.y;
            o[0].z += p0.x*v0.z + p0.y*v1.z + p0.z*v2.z + p0.w*v3.z;
            o[0].w += p0.x*v0.w + p0.y*v1.w + p0.z*v2.w + p0.w*v3.w;

            o[1].x += p1.x*v0.x + p1.y*v1.x + p1.z*v2.x + p1.w*v3.x;
            o[1].y += p1.x*v0.y + p1.y*v1.y + p1.z*v2.y + p1.w*v3.y;
            o[1].z += p1.x*v0.z + p1.y*v1.z + p1.z*v2.z + p1.w*v3.z;
            o[1].w += p1.x*v0.w + p1.y*v1.w + p1.z*v2.w + p1.w*v3.w;

            o[2].x += p2.x*v0.x + p2.y*v1.x + p2.z*v2.x + p2.w*v3.x;
            o[2].y += p2.x*v0.y + p2.y*v1.y + p2.z*v2.y + p2.w*v3.y;
            o[2].z += p2.x*v0.z + p2.y*v1.z + p2.z*v2.z + p2.w*v3.z;
            o[2].w += p2.x*v0.w + p2.y*v1.w + p2.z*v2.w + p2.w*v3.w;

            o[3].x += p3.x*v0.x + p3.y*v1.x + p3.z*v2.x + p3.w*v3.x;
            o[3].y += p3.x*v0.y + p3.y*v1.y + p3.z*v2.y + p3.w*v3.y;
            o[3].z += p3.x*v0.z + p3.y*v1.z + p3.z*v2.z + p3.w*v3.z;
            o[3].w += p3.x*v0.w + p3.y*v1.w + p3.z*v2.w + p3.w*v3.w;
        }
    }

    #pragma unroll
    for (int rr = 0; rr < 4; rr++) {
        float inv = 1.0f / l[rr];
        float4 r4 = make_float4(o[rr].x * inv, o[rr].y * inv, o[rr].z * inv, o[rr].w * inv);
        *(float4*)(Yg + (size_t)(qb + cy * 4 + rr) * HD + cx * 4) = r4;
    }
}

// ---------------------------------------------------------------------------
extern "C" void kernel_launch(void* const* d_in, const int* in_sizes, int n_in,
                              void* d_out, int out_size)
{
    const float* x    = (const float*)d_in[0];
    const float* cosp = (const float*)d_in[1];
    const float* sinp = (const float*)d_in[2];
    const int*   tmsk = (const int*)  d_in[3];
    const float* Wq   = (const float*)d_in[4];
    const float* Wk   = (const float*)d_in[5];
    const float* Wv   = (const float*)d_in[6];
    const float* Wpr  = (const float*)d_in[7];
    const float* mbr  = (const float*)d_in[8];
    const int*   bsp  = (const int*)  d_in[9];
    float* out = (float*)d_out;

    dim3 gg(BATCH * SEQ / 64, NH);   // 128 x 6
    gemm_kernel<0, 0, true ><<<gg, 256>>>(x, Wq, cosp, sinp, nullptr);
    gemm_kernel<0, 1, true ><<<gg, 256>>>(x, Wk, cosp, sinp, nullptr);
    gemm_kernel<0, 2, false><<<gg, 256>>>(x, Wv, nullptr, nullptr, nullptr);

    attn_kernel<<<dim3(SEQ / 64, BATCH * NH), 256>>>(tmsk, mbr, bsp);

    gemm_kernel<1, 3, false><<<gg, 256>>>(nullptr, Wpr, nullptr, nullptr, out);
}

// round 4
// speedup vs baseline: 1.8787x; 1.8787x over previous
#include <cuda_runtime.h>
#include <cuda_fp16.h>
#include <math.h>
#include <stdint.h>

#define BATCH 4
#define SEQ   2048
#define CDIM  384
#define NH    6
#define HD    64

// Scratch (static __device__ arrays — no runtime allocation allowed).
__device__ float g_q[BATCH*NH*SEQ*HD];
__device__ float g_k[BATCH*NH*SEQ*HD];
__device__ float g_v[BATCH*NH*SEQ*HD];
__device__ float g_y[BATCH*NH*SEQ*HD];

// ---------------------------------------------------------------------------
// mma.sync / ldmatrix helpers (sm_80-compatible PTX; assembles for sm_100).
// ---------------------------------------------------------------------------
__device__ __forceinline__ uint32_t smem_u32(const void* p) {
    uint32_t a;
    asm("{ .reg .u64 t; cvta.to.shared.u64 t, %1; cvt.u32.u64 %0, t; }"
        : "=r"(a) : "l"(p));
    return a;
}
__device__ __forceinline__ void ldsm_x4(uint32_t& r0, uint32_t& r1,
                                        uint32_t& r2, uint32_t& r3, uint32_t addr) {
    asm volatile("ldmatrix.sync.aligned.m8n8.x4.shared.b16 {%0,%1,%2,%3}, [%4];"
                 : "=r"(r0), "=r"(r1), "=r"(r2), "=r"(r3) : "r"(addr));
}
__device__ __forceinline__ void ldsm_x4_t(uint32_t& r0, uint32_t& r1,
                                          uint32_t& r2, uint32_t& r3, uint32_t addr) {
    asm volatile("ldmatrix.sync.aligned.m8n8.x4.trans.shared.b16 {%0,%1,%2,%3}, [%4];"
                 : "=r"(r0), "=r"(r1), "=r"(r2), "=r"(r3) : "r"(addr));
}
__device__ __forceinline__ void mma16816(float* d,
    uint32_t a0, uint32_t a1, uint32_t a2, uint32_t a3, uint32_t b0, uint32_t b1) {
    asm volatile(
        "mma.sync.aligned.m16n8k16.row.col.f32.f16.f16.f32 "
        "{%0,%1,%2,%3}, {%4,%5,%6,%7}, {%8,%9}, {%0,%1,%2,%3};"
        : "+f"(d[0]), "+f"(d[1]), "+f"(d[2]), "+f"(d[3])
        : "r"(a0), "r"(a1), "r"(a2), "r"(a3), "r"(b0), "r"(b1));
}
__device__ __forceinline__ uint32_t pack_h2(float x, float y) {
    __half2 h = __floats2half2_rn(x, y);
    return *reinterpret_cast<uint32_t*>(&h);
}
__device__ __forceinline__ float lo_res(float x) {
    return x - __half2float(__float2half_rn(x));
}

// ---------------------------------------------------------------------------
// GEMM: out[r, j] = sum_c A[r, c] * W[j, c]   (unchanged; passing since R2)
// ---------------------------------------------------------------------------
template<int SRC, int DST, bool ROPE>
__global__ __launch_bounds__(256)
void gemm_kernel(const float* __restrict__ A,
                 const float* __restrict__ W,
                 const float* __restrict__ cosp,
                 const float* __restrict__ sinp,
                 float* __restrict__ outp)
{
    __shared__ float As[32][65];
    __shared__ float Bs[32][65];

    const int tid = threadIdx.x;
    const int tx  = tid & 15;
    const int ty  = tid >> 4;
    const int rbase = blockIdx.x * 64;
    const int jb    = blockIdx.y * 64;

    float acc[4][4];
    #pragma unroll
    for (int i = 0; i < 4; i++)
        #pragma unroll
        for (int j = 0; j < 4; j++) acc[i][j] = 0.0f;

    const int lc = tid & 31;
    const int lr = tid >> 5;

    for (int kb = 0; kb < CDIM; kb += 32) {
        #pragma unroll
        for (int it = 0; it < 8; it++) {
            int rl = lr + it * 8;
            int r  = rbase + rl;
            float av;
            if (SRC == 1) {
                int bb = r >> 11, t = r & (SEQ - 1);
                int cc = kb + lc;
                av = g_y[((size_t)(bb * NH + (cc >> 6)) * SEQ + t) * HD + (cc & 63)];
            } else {
                av = A[(size_t)r * CDIM + kb + lc];
            }
            As[lc][rl] = av;
            Bs[lc][rl] = W[(size_t)(jb + rl) * CDIM + kb + lc];
        }
        __syncthreads();
        #pragma unroll
        for (int k = 0; k < 32; k++) {
            float a0 = As[k][ty], a1 = As[k][ty + 16], a2 = As[k][ty + 32], a3 = As[k][ty + 48];
            float b0 = Bs[k][tx], b1 = Bs[k][tx + 16], b2 = Bs[k][tx + 32], b3 = Bs[k][tx + 48];
            acc[0][0] += a0 * b0; acc[0][1] += a0 * b1; acc[0][2] += a0 * b2; acc[0][3] += a0 * b3;
            acc[1][0] += a1 * b0; acc[1][1] += a1 * b1; acc[1][2] += a1 * b2; acc[1][3] += a1 * b3;
            acc[2][0] += a2 * b0; acc[2][1] += a2 * b1; acc[2][2] += a2 * b2; acc[2][3] += a2 * b3;
            acc[3][0] += a3 * b0; acc[3][1] += a3 * b1; acc[3][2] += a3 * b2; acc[3][3] += a3 * b3;
        }
        __syncthreads();
    }

    #pragma unroll
    for (int i = 0; i < 4; i++) {
        int r = rbase + ty + 16 * i;
        float v0 = acc[i][0], v1 = acc[i][1], v2 = acc[i][2], v3 = acc[i][3];
        if (ROPE) {
            int t = r & (SEQ - 1);
            float c0 = cosp[t * 32 + tx],      s0 = sinp[t * 32 + tx];
            float c1 = cosp[t * 32 + tx + 16], s1 = sinp[t * 32 + tx + 16];
            float n0 =  v0 * c0 + v2 * s0;
            float n2 = -v0 * s0 + v2 * c0;
            float n1 =  v1 * c1 + v3 * s1;
            float n3 = -v1 * s1 + v3 * c1;
            float ss = n0 * n0 + n1 * n1 + n2 * n2 + n3 * n3;
            ss += __shfl_xor_sync(0xffffffffu, ss, 1);
            ss += __shfl_xor_sync(0xffffffffu, ss, 2);
            ss += __shfl_xor_sync(0xffffffffu, ss, 4);
            ss += __shfl_xor_sync(0xffffffffu, ss, 8);
            float rn = rsqrtf(ss * (1.0f / HD) + 1.1920929e-07f);
            v0 = n0 * rn; v1 = n1 * rn; v2 = n2 * rn; v3 = n3 * rn;
        }
        if (DST == 3) {
            float* o = outp + (size_t)r * CDIM + jb;
            o[tx] = v0; o[tx + 16] = v1; o[tx + 32] = v2; o[tx + 48] = v3;
        } else {
            float* base = (DST == 0) ? g_q : (DST == 1) ? g_k : g_v;
            int bb = r >> 11, t = r & (SEQ - 1);
            float* o = base + ((size_t)(bb * NH + blockIdx.y) * SEQ + t) * HD;
            o[tx] = v0; o[tx + 16] = v1; o[tx + 32] = v2; o[tx + 48] = v3;
        }
    }
}

// ===========================================================================
// Tensor-core flash attention via mma.sync m16n8k16 fp16 (f32 accum).
//   CTA: 128 q-rows x one (b,h). 8 warps, each owns 16 q-rows.
//   KV tiles of 64. K converted to fp16 hi+lo (QK = 3 MMAs: hh + lo_q*h + h*lo_k),
//   P split hi/lo (PV = 2 MMAs), V single fp16.
//   Static softmax shift: q,k RMS-normed => |s*0.125| <= 8, |bias| <= 2;
//   p = exp(s*0.125 + bias - 4) in [e^-14, e^6] (fp16-safe); O accumulates
//   in f32 fragments, one normalization at the end.
//   smem tiles row-major [j][d], 128B rows, sw128 XOR swizzle => conflict-free
//   ldmatrix.
// ===========================================================================
__global__ __launch_bounds__(256)
void attn_kernel(const int* __restrict__ tmask,
                 const float* __restrict__ mb_raw,
                 const int* __restrict__ bsp)
{
    __shared__ __align__(1024) char s_buf[3 * 8192];   // Khi, Klo, Vhi
    __shared__ int s_mj[64];

    char* Khi = s_buf;
    char* Klo = s_buf + 8192;
    char* Vhi = s_buf + 16384;

    const int tid  = threadIdx.x;
    const int w    = tid >> 5;
    const int lane = tid & 31;
    const int bh   = blockIdx.y;
    const int b    = bh / NH;
    const int h    = bh - b * NH;
    const int qb   = blockIdx.x * 128;

    const float* Qg = g_q + (size_t)bh * SEQ * HD;
    const float* Kg = g_k + (size_t)bh * SEQ * HD;
    const float* Vg = g_v + (size_t)bh * SEQ * HD;
    float*       Yg = g_y + (size_t)bh * SEQ * HD;

    // ---- bias constants ----
    float bs;
    {
        int iv = bsp[0];
        bs = (iv > -1000000 && iv < 1000000) ? (float)iv : __int_as_float(iv);
    }
    float G1 = 0.5f * tanhf(mb_raw[h * 3 + 0]) * bs;
    float G2 = 0.5f * tanhf(mb_raw[h * 3 + 1]) * bs;
    float G3 = 0.5f * tanhf(mb_raw[h * 3 + 2]) * bs;
    const float b01 = fminf(2.0f, fmaxf(-2.0f, G2));
    const float b10 = fminf(2.0f, fmaxf(-2.0f, G1));
    const float b11 = fminf(2.0f, fmaxf(-2.0f, G1 + G2 + G3));

    // ---- per-lane rows, mask-in bias (fold in the -4 softmax shift) ----
    const int rA = qb + w * 16 + (lane >> 2);      // global q row (A), B = +8
    const int cb = (lane & 3) * 2;                 // col base within 8-block
    const int miA = tmask[b * SEQ + rA];
    const int miB = tmask[b * SEQ + rA + 8];
    const float bm0A = (miA ? b10 : 0.0f) - 4.0f;
    const float bm1A = (miA ? b11 : b01 ) - 4.0f;
    const float bm0B = (miB ? b10 : 0.0f) - 4.0f;
    const float bm1B = (miB ? b11 : b01 ) - 4.0f;

    // ---- Q fragments (hi + lo), kept in registers for the whole kernel ----
    uint32_t qhi[16], qlo[16];
    {
        const float* qA = Qg + (size_t)rA * HD + cb;
        const float* qB = qA + 8 * HD;
        #pragma unroll
        for (int kc = 0; kc < 4; kc++) {
            float2 fA0 = *(const float2*)(qA + kc * 16);
            float2 fB0 = *(const float2*)(qB + kc * 16);
            float2 fA1 = *(const float2*)(qA + kc * 16 + 8);
            float2 fB1 = *(const float2*)(qB + kc * 16 + 8);
            qhi[kc*4+0] = pack_h2(fA0.x, fA0.y);
            qhi[kc*4+1] = pack_h2(fB0.x, fB0.y);
            qhi[kc*4+2] = pack_h2(fA1.x, fA1.y);
            qhi[kc*4+3] = pack_h2(fB1.x, fB1.y);
            qlo[kc*4+0] = pack_h2(lo_res(fA0.x), lo_res(fA0.y));
            qlo[kc*4+1] = pack_h2(lo_res(fB0.x), lo_res(fB0.y));
            qlo[kc*4+2] = pack_h2(lo_res(fA1.x), lo_res(fA1.y));
            qlo[kc*4+3] = pack_h2(lo_res(fB1.x), lo_res(fB1.y));
        }
    }

    // ---- ldmatrix per-lane address components ----
    // QK (non-trans): tiles (j0,d0),(j0,d0+8),(j0+8,d0),(j0+8,d0+8)
    const int joK = (lane & 7) + ((lane >> 4) & 1) * 8;
    const int doK = ((lane >> 3) & 1) * 8;
    const uint32_t lK  = (uint32_t)(joK * 128 + doK * 2);
    const uint32_t xK  = (uint32_t)((joK & 7) << 4);
    // PV (trans): tiles (j0,d0),(j0+8,d0),(j0,d0+8),(j0+8,d0+8)
    const int joV = (lane & 7) + ((lane >> 3) & 1) * 8;
    const int doV = ((lane >> 4) & 1) * 8;
    const uint32_t lV  = (uint32_t)(joV * 128 + doV * 2);
    const uint32_t xV  = (uint32_t)((joV & 7) << 4);

    const uint32_t khiA = smem_u32(Khi);
    const uint32_t kloA = smem_u32(Klo);
    const uint32_t vhiA = smem_u32(Vhi);

    float o[8][4];
    #pragma unroll
    for (int i = 0; i < 8; i++)
        #pragma unroll
        for (int jx = 0; jx < 4; jx++) o[i][jx] = 0.0f;
    float lA = 0.0f, lB = 0.0f;

    const int jc = tid >> 2;        // convert: row 0..63
    const int dg = tid & 3;         // convert: d-group (16 floats)
    const uint32_t coff  = (uint32_t)(jc * 128 + dg * 32);
    const uint32_t cxor  = (uint32_t)((jc & 7) << 4);

    for (int kt = 0; kt < SEQ / 64; kt++) {
        __syncthreads();   // previous tile fully consumed (frags in regs)

        // ---- convert K (hi+lo) and V (hi) tiles to fp16 smem ----
        {
            const float* kr = Kg + ((size_t)(kt * 64 + jc)) * HD + dg * 16;
            float4 f0 = *(const float4*)(kr + 0);
            float4 f1 = *(const float4*)(kr + 4);
            float4 f2 = *(const float4*)(kr + 8);
            float4 f3 = *(const float4*)(kr + 12);
            uint4 h0, h1, l0, l1;
            h0.x = pack_h2(f0.x, f0.y); h0.y = pack_h2(f0.z, f0.w);
            h0.z = pack_h2(f1.x, f1.y); h0.w = pack_h2(f1.z, f1.w);
            h1.x = pack_h2(f2.x, f2.y); h1.y = pack_h2(f2.z, f2.w);
            h1.z = pack_h2(f3.x, f3.y); h1.w = pack_h2(f3.z, f3.w);
            l0.x = pack_h2(lo_res(f0.x), lo_res(f0.y)); l0.y = pack_h2(lo_res(f0.z), lo_res(f0.w));
            l0.z = pack_h2(lo_res(f1.x), lo_res(f1.y)); l0.w = pack_h2(lo_res(f1.z), lo_res(f1.w));
            l1.x = pack_h2(lo_res(f2.x), lo_res(f2.y)); l1.y = pack_h2(lo_res(f2.z), lo_res(f2.w));
            l1.z = pack_h2(lo_res(f3.x), lo_res(f3.y)); l1.w = pack_h2(lo_res(f3.z), lo_res(f3.w));
            *(uint4*)(Khi + ( coff       ^ cxor)) = h0;
            *(uint4*)(Khi + ((coff + 16) ^ cxor)) = h1;
            *(uint4*)(Klo + ( coff       ^ cxor)) = l0;
            *(uint4*)(Klo + ((coff + 16) ^ cxor)) = l1;

            const float* vr = Vg + ((size_t)(kt * 64 + jc)) * HD + dg * 16;
            float4 g0 = *(const float4*)(vr + 0);
            float4 g1 = *(const float4*)(vr + 4);
            float4 g2 = *(const float4*)(vr + 8);
            float4 g3 = *(const float4*)(vr + 12);
            uint4 v0, v1;
            v0.x = pack_h2(g0.x, g0.y); v0.y = pack_h2(g0.z, g0.w);
            v0.z = pack_h2(g1.x, g1.y); v0.w = pack_h2(g1.z, g1.w);
            v1.x = pack_h2(g2.x, g2.y); v1.y = pack_h2(g2.z, g2.w);
            v1.z = pack_h2(g3.x, g3.y); v1.w = pack_h2(g3.z, g3.w);
            *(uint4*)(Vhi + ( coff       ^ cxor)) = v0;
            *(uint4*)(Vhi + ((coff + 16) ^ cxor)) = v1;

            if (tid < 64) s_mj[tid] = tmask[b * SEQ + kt * 64 + tid];
        }
        __syncthreads();

        // ---- S = Q K^T (hi*hi + lo*hi + hi*lo) ----
        float sf[8][4];
        #pragma unroll
        for (int i = 0; i < 8; i++)
            #pragma unroll
            for (int jx = 0; jx < 4; jx++) sf[i][jx] = 0.0f;

        #pragma unroll
        for (int nb2 = 0; nb2 < 4; nb2++) {
            #pragma unroll
            for (int kc = 0; kc < 4; kc++) {
                uint32_t off = (uint32_t)(nb2 * 2048 + kc * 32) + lK;
                uint32_t bh0, bh1, bh2, bh3;
                ldsm_x4(bh0, bh1, bh2, bh3, (khiA + off) ^ xK);
                mma16816(sf[2*nb2],   qhi[kc*4+0], qhi[kc*4+1], qhi[kc*4+2], qhi[kc*4+3], bh0, bh1);
                mma16816(sf[2*nb2+1], qhi[kc*4+0], qhi[kc*4+1], qhi[kc*4+2], qhi[kc*4+3], bh2, bh3);
                mma16816(sf[2*nb2],   qlo[kc*4+0], qlo[kc*4+1], qlo[kc*4+2], qlo[kc*4+3], bh0, bh1);
                mma16816(sf[2*nb2+1], qlo[kc*4+0], qlo[kc*4+1], qlo[kc*4+2], qlo[kc*4+3], bh2, bh3);
                uint32_t bl0, bl1, bl2, bl3;
                ldsm_x4(bl0, bl1, bl2, bl3, (kloA + off) ^ xK);
                mma16816(sf[2*nb2],   qhi[kc*4+0], qhi[kc*4+1], qhi[kc*4+2], qhi[kc*4+3], bl0, bl1);
                mma16816(sf[2*nb2+1], qhi[kc*4+0], qhi[kc*4+1], qhi[kc*4+2], qhi[kc*4+3], bl2, bl3);
            }
        }

        // ---- softmax: p = exp(s*0.125 + bias - 4); P -> hi/lo fragments ----
        uint32_t phi[16], plo[16];
        #pragma unroll
        for (int nb = 0; nb < 8; nb++) {
            int j0 = nb * 8 + cb;
            int mj0 = s_mj[j0], mj1 = s_mj[j0 + 1];
            float bA0 = mj0 ? bm1A : bm0A;
            float bA1 = mj1 ? bm1A : bm0A;
            float bB0 = mj0 ? bm1B : bm0B;
            float bB1 = mj1 ? bm1B : bm0B;
            float pA0 = __expf(fmaf(sf[nb][0], 0.125f, bA0));
            float pA1 = __expf(fmaf(sf[nb][1], 0.125f, bA1));
            float pB0 = __expf(fmaf(sf[nb][2], 0.125f, bB0));
            float pB1 = __expf(fmaf(sf[nb][3], 0.125f, bB1));
            lA += pA0 + pA1;
            lB += pB0 + pB1;
            phi[nb*2+0] = pack_h2(pA0, pA1);
            phi[nb*2+1] = pack_h2(pB0, pB1);
            plo[nb*2+0] = pack_h2(lo_res(pA0), lo_res(pA1));
            plo[nb*2+1] = pack_h2(lo_res(pB0), lo_res(pB1));
        }

        // ---- O += P V  (Phi*V + Plo*V) ----
        #pragma unroll
        for (int db2 = 0; db2 < 4; db2++) {
            #pragma unroll
            for (int kc = 0; kc < 4; kc++) {
                uint32_t off = (uint32_t)(kc * 2048 + db2 * 32) + lV;
                uint32_t v0, v1, v2, v3;
                ldsm_x4_t(v0, v1, v2, v3, (vhiA + off) ^ xV);
                mma16816(o[2*db2],   phi[4*kc+0], phi[4*kc+1], phi[4*kc+2], phi[4*kc+3], v0, v1);
                mma16816(o[2*db2+1], phi[4*kc+0], phi[4*kc+1], phi[4*kc+2], phi[4*kc+3], v2, v3);
                mma16816(o[2*db2],   plo[4*kc+0], plo[4*kc+1], plo[4*kc+2], plo[4*kc+3], v0, v1);
                mma16816(o[2*db2+1], plo[4*kc+0], plo[4*kc+1], plo[4*kc+2], plo[4*kc+3], v2, v3);
            }
        }
    }

    // ---- epilogue: reduce l across the quad, normalize, store ----
    lA += __shfl_xor_sync(0xffffffffu, lA, 1);
    lA += __shfl_xor_sync(0xffffffffu, lA, 2);
    lB += __shfl_xor_sync(0xffffffffu, lB, 1);
    lB += __shfl_xor_sync(0xffffffffu, lB, 2);
    float iA = 1.0f / lA, iB = 1.0f / lB;

    float* yA = Yg + (size_t)rA * HD + cb;
    float* yB = yA + 8 * HD;
    #pragma unroll
    for (int db = 0; db < 8; db++) {
        float2 a = make_float2(o[db][0] * iA, o[db][1] * iA);
        float2 c = make_float2(o[db][2] * iB, o[db][3] * iB);
        *(float2*)(yA + db * 8) = a;
        *(float2*)(yB + db * 8) = c;
    }
}

// ---------------------------------------------------------------------------
extern "C" void kernel_launch(void* const* d_in, const int* in_sizes, int n_in,
                              void* d_out, int out_size)
{
    const float* x    = (const float*)d_in[0];
    const float* cosp = (const float*)d_in[1];
    const float* sinp = (const float*)d_in[2];
    const int*   tmsk = (const int*)  d_in[3];
    const float* Wq   = (const float*)d_in[4];
    const float* Wk   = (const float*)d_in[5];
    const float* Wv   = (const float*)d_in[6];
    const float* Wpr  = (const float*)d_in[7];
    const float* mbr  = (const float*)d_in[8];
    const int*   bsp  = (const int*)  d_in[9];
    float* out = (float*)d_out;

    dim3 gg(BATCH * SEQ / 64, NH);   // 128 x 6
    gemm_kernel<0, 0, true ><<<gg, 256>>>(x, Wq, cosp, sinp, nullptr);
    gemm_kernel<0, 1, true ><<<gg, 256>>>(x, Wk, cosp, sinp, nullptr);
    gemm_kernel<0, 2, false><<<gg, 256>>>(x, Wv, nullptr, nullptr, nullptr);

    attn_kernel<<<dim3(SEQ / 128, BATCH * NH), 256>>>(tmsk, mbr, bsp);

    gemm_kernel<1, 3, false><<<gg, 256>>>(nullptr, Wpr, nullptr, nullptr, out);
}

// round 5
// speedup vs baseline: 2.9672x; 1.5794x over previous
#include <cuda_runtime.h>
#include <cuda_fp16.h>
#include <math.h>
#include <stdint.h>

#define BATCH 4
#define SEQ   2048
#define CDIM  384
#define NH    6
#define HD    64

// Scratch (static __device__ arrays — no runtime allocation allowed).
__device__ float g_q[BATCH*NH*SEQ*HD];
__device__ float g_k[BATCH*NH*SEQ*HD];
__device__ float g_v[BATCH*NH*SEQ*HD];
__device__ float g_y[BATCH*NH*SEQ*HD];

// ---------------------------------------------------------------------------
// mma.sync / ldmatrix helpers (sm_80-compatible PTX; assembles for sm_100).
// ---------------------------------------------------------------------------
__device__ __forceinline__ uint32_t smem_u32(const void* p) {
    uint32_t a;
    asm("{ .reg .u64 t; cvta.to.shared.u64 t, %1; cvt.u32.u64 %0, t; }"
        : "=r"(a) : "l"(p));
    return a;
}
__device__ __forceinline__ void ldsm_x4(uint32_t& r0, uint32_t& r1,
                                        uint32_t& r2, uint32_t& r3, uint32_t addr) {
    asm volatile("ldmatrix.sync.aligned.m8n8.x4.shared.b16 {%0,%1,%2,%3}, [%4];"
                 : "=r"(r0), "=r"(r1), "=r"(r2), "=r"(r3) : "r"(addr));
}
__device__ __forceinline__ void ldsm_x4_t(uint32_t& r0, uint32_t& r1,
                                          uint32_t& r2, uint32_t& r3, uint32_t addr) {
    asm volatile("ldmatrix.sync.aligned.m8n8.x4.trans.shared.b16 {%0,%1,%2,%3}, [%4];"
                 : "=r"(r0), "=r"(r1), "=r"(r2), "=r"(r3) : "r"(addr));
}
__device__ __forceinline__ void mma16816(float* d,
    uint32_t a0, uint32_t a1, uint32_t a2, uint32_t a3, uint32_t b0, uint32_t b1) {
    asm volatile(
        "mma.sync.aligned.m16n8k16.row.col.f32.f16.f16.f32 "
        "{%0,%1,%2,%3}, {%4,%5,%6,%7}, {%8,%9}, {%0,%1,%2,%3};"
        : "+f"(d[0]), "+f"(d[1]), "+f"(d[2]), "+f"(d[3])
        : "r"(a0), "r"(a1), "r"(a2), "r"(a3), "r"(b0), "r"(b1));
}
__device__ __forceinline__ uint32_t pack_h2(float x, float y) {
    __half2 h = __floats2half2_rn(x, y);
    return *reinterpret_cast<uint32_t*>(&h);
}
__device__ __forceinline__ float lo_res(float x) {
    return x - __half2float(__float2half_rn(x));
}
// 64-byte-row swizzle (16B granules): g' = g ^ row-derived bits -> conflict-free ldmatrix
__device__ __forceinline__ uint32_t sw64(uint32_t off) {
    return off ^ ((off >> 3) & 0x30);
}

// ===========================================================================
// Tensor-core GEMM: out[r, j] = sum_c A[r, c] * W[j, c]
//   Both operands hi/lo fp16 split (3 MMAs) -> ~fp32 accuracy.
//   Tile: 128(M) x 64(N) x 32(K). 256 threads, 8 warps; warp owns 16 rows.
//   SRC 0: A = x [B*T, C].  SRC 1: gather from g_y [B,H,T,D].
//   DST 0/1/2: g_q/g_k/g_v [B,H,T,D] (blockIdx.y = head), ROPE+RMSNorm epilogue.
//   DST 3: outp [B,T,C].
// ===========================================================================
template<int SRC, int DST, bool ROPE>
__global__ __launch_bounds__(256, 2)
void gemm_tc(const float* __restrict__ A,
             const float* __restrict__ W,
             const float* __restrict__ cosp,
             const float* __restrict__ sinp,
             float* __restrict__ outp)
{
    __shared__ __align__(16) char sAhi[8192];   // [128][32] fp16, 64B rows
    __shared__ __align__(16) char sAlo[8192];
    __shared__ __align__(16) char sWhi[4096];   // [64][32] fp16
    __shared__ __align__(16) char sWlo[4096];

    const int tid  = threadIdx.x;
    const int w    = tid >> 5;
    const int lane = tid & 31;
    const int rbase = blockIdx.x * 128;
    const int jb    = blockIdx.y * 64;

    const uint32_t aHi = smem_u32(sAhi);
    const uint32_t aLo = smem_u32(sAlo);
    const uint32_t wHi = smem_u32(sWhi);
    const uint32_t wLo = smem_u32(sWlo);

    float acc[8][4];
    #pragma unroll
    for (int m = 0; m < 8; m++)
        #pragma unroll
        for (int i = 0; i < 4; i++) acc[m][i] = 0.0f;

    // ldmatrix lane addressing
    const uint32_t aoff = (uint32_t)((w * 16 + (lane & 15)) * 64 + ((lane >> 4) & 1) * 16);
    const int joK = (lane & 7) + ((lane >> 4) & 1) * 8;
    const int doK = ((lane >> 3) & 1) * 8;

    // loaders
    const int rl = tid >> 1;               // A: row 0..127
    const int ko = (tid & 1) * 16;         // A: k offset 0/16
    const int rw = tid >> 2;               // W: row 0..63
    const int kw = (tid & 3) * 8;          // W: k offset 0/8/16/24

    for (int kb = 0; kb < CDIM; kb += 32) {
        __syncthreads();
        // ---- stage A tile (hi+lo) ----
        {
            const float* src;
            int rg = rbase + rl;
            if (SRC == 1) {
                int bb = rg >> 11, t = rg & (SEQ - 1);
                int c0 = kb + ko;
                src = g_y + ((size_t)(bb * NH + (c0 >> 6)) * SEQ + t) * HD + (c0 & 63);
            } else {
                src = A + (size_t)rg * CDIM + kb + ko;
            }
            float4 f0 = *(const float4*)(src + 0);
            float4 f1 = *(const float4*)(src + 4);
            float4 f2 = *(const float4*)(src + 8);
            float4 f3 = *(const float4*)(src + 12);
            uint4 h0, h1, l0, l1;
            h0.x = pack_h2(f0.x, f0.y); h0.y = pack_h2(f0.z, f0.w);
            h0.z = pack_h2(f1.x, f1.y); h0.w = pack_h2(f1.z, f1.w);
            h1.x = pack_h2(f2.x, f2.y); h1.y = pack_h2(f2.z, f2.w);
            h1.z = pack_h2(f3.x, f3.y); h1.w = pack_h2(f3.z, f3.w);
            l0.x = pack_h2(lo_res(f0.x), lo_res(f0.y)); l0.y = pack_h2(lo_res(f0.z), lo_res(f0.w));
            l0.z = pack_h2(lo_res(f1.x), lo_res(f1.y)); l0.w = pack_h2(lo_res(f1.z), lo_res(f1.w));
            l1.x = pack_h2(lo_res(f2.x), lo_res(f2.y)); l1.y = pack_h2(lo_res(f2.z), lo_res(f2.w));
            l1.z = pack_h2(lo_res(f3.x), lo_res(f3.y)); l1.w = pack_h2(lo_res(f3.z), lo_res(f3.w));
            uint32_t g = (uint32_t)(rl * 64 + ko * 2);
            *(uint4*)(sAhi + sw64(g))      = h0;
            *(uint4*)(sAhi + sw64(g + 16)) = h1;
            *(uint4*)(sAlo + sw64(g))      = l0;
            *(uint4*)(sAlo + sw64(g + 16)) = l1;
        }
        // ---- stage W tile (hi+lo) ----
        {
            const float* src = W + (size_t)(jb + rw) * CDIM + kb + kw;
            float4 f0 = *(const float4*)(src + 0);
            float4 f1 = *(const float4*)(src + 4);
            uint4 hh, ll;
            hh.x = pack_h2(f0.x, f0.y); hh.y = pack_h2(f0.z, f0.w);
            hh.z = pack_h2(f1.x, f1.y); hh.w = pack_h2(f1.z, f1.w);
            ll.x = pack_h2(lo_res(f0.x), lo_res(f0.y)); ll.y = pack_h2(lo_res(f0.z), lo_res(f0.w));
            ll.z = pack_h2(lo_res(f1.x), lo_res(f1.y)); ll.w = pack_h2(lo_res(f1.z), lo_res(f1.w));
            uint32_t g = (uint32_t)(rw * 64 + kw * 2);
            *(uint4*)(sWhi + sw64(g)) = hh;
            *(uint4*)(sWlo + sw64(g)) = ll;
        }
        __syncthreads();

        #pragma unroll
        for (int kc = 0; kc < 2; kc++) {
            uint32_t ah0, ah1, ah2, ah3, al0, al1, al2, al3;
            ldsm_x4(ah0, ah1, ah2, ah3, aHi + sw64(aoff + kc * 32));
            ldsm_x4(al0, al1, al2, al3, aLo + sw64(aoff + kc * 32));
            #pragma unroll
            for (int cg = 0; cg < 4; cg++) {
                uint32_t boff = sw64((uint32_t)((cg * 16 + joK) * 64 + kc * 32 + doK * 2));
                uint32_t bh0, bh1, bh2, bh3;
                ldsm_x4(bh0, bh1, bh2, bh3, wHi + boff);
                mma16816(acc[2*cg],   ah0, ah1, ah2, ah3, bh0, bh1);
                mma16816(acc[2*cg+1], ah0, ah1, ah2, ah3, bh2, bh3);
                mma16816(acc[2*cg],   al0, al1, al2, al3, bh0, bh1);
                mma16816(acc[2*cg+1], al0, al1, al2, al3, bh2, bh3);
                uint32_t bl0, bl1, bl2, bl3;
                ldsm_x4(bl0, bl1, bl2, bl3, wLo + boff);
                mma16816(acc[2*cg],   ah0, ah1, ah2, ah3, bl0, bl1);
                mma16816(acc[2*cg+1], ah0, ah1, ah2, ah3, bl2, bl3);
            }
        }
    }

    // ---- epilogue ----
    // acc[m][i]: col = (m>>1)*16 + (m&1)*8 + (lane&3)*2 + (i&1); rows rA (i<2), rA+8.
    const int rA = rbase + w * 16 + (lane >> 2);
    const int cb = (lane & 3) * 2;

    #pragma unroll
    for (int rp = 0; rp < 2; rp++) {              // rp=0 -> row rA, rp=1 -> row rA+8
        int r = rA + rp * 8;
        int i0 = rp * 2;
        if (ROPE) {
            int t = r & (SEQ - 1);
            #pragma unroll
            for (int m = 0; m < 4; m++) {
                int d0 = (m >> 1) * 16 + (m & 1) * 8 + cb;
                float c0 = cosp[t * 32 + d0],     s0 = sinp[t * 32 + d0];
                float c1 = cosp[t * 32 + d0 + 1], s1 = sinp[t * 32 + d0 + 1];
                float x1 = acc[m][i0],     x2 = acc[m+4][i0];
                acc[m][i0]     =  x1 * c0 + x2 * s0;
                acc[m+4][i0]   = -x1 * s0 + x2 * c0;
                float y1 = acc[m][i0+1],   y2 = acc[m+4][i0+1];
                acc[m][i0+1]   =  y1 * c1 + y2 * s1;
                acc[m+4][i0+1] = -y1 * s1 + y2 * c1;
            }
            float ss = 0.0f;
            #pragma unroll
            for (int m = 0; m < 8; m++)
                ss += acc[m][i0]*acc[m][i0] + acc[m][i0+1]*acc[m][i0+1];
            ss += __shfl_xor_sync(0xffffffffu, ss, 1);
            ss += __shfl_xor_sync(0xffffffffu, ss, 2);
            float rn = rsqrtf(ss * (1.0f / HD) + 1.1920929e-07f);
            #pragma unroll
            for (int m = 0; m < 8; m++) { acc[m][i0] *= rn; acc[m][i0+1] *= rn; }
        }
        float* o;
        if (DST == 3) {
            o = outp + (size_t)r * CDIM + jb;
        } else {
            float* base = (DST == 0) ? g_q : (DST == 1) ? g_k : g_v;
            int bb = r >> 11, t = r & (SEQ - 1);
            o = base + ((size_t)(bb * NH + blockIdx.y) * SEQ + t) * HD;
        }
        #pragma unroll
        for (int m = 0; m < 8; m++) {
            int d0 = (m >> 1) * 16 + (m & 1) * 8 + cb;
            *(float2*)(o + d0) = make_float2(acc[m][i0], acc[m][i0+1]);
        }
    }
}

// ===========================================================================
// Tensor-core flash attention (mma.sync m16n8k16 fp16, f32 accum).
//   Restructured into two 32-col halves per KV tile to shrink live ranges;
//   __launch_bounds__(256,2) targets 2 CTAs/SM (R4 was regs=174 -> occ 12.5%).
// ===========================================================================
__global__ __launch_bounds__(256, 2)
void attn_kernel(const int* __restrict__ tmask,
                 const float* __restrict__ mb_raw,
                 const int* __restrict__ bsp)
{
    __shared__ __align__(1024) char s_buf[3 * 8192];   // Khi, Klo, Vhi
    __shared__ int s_mj[64];

    char* Khi = s_buf;
    char* Klo = s_buf + 8192;
    char* Vhi = s_buf + 16384;

    const int tid  = threadIdx.x;
    const int w    = tid >> 5;
    const int lane = tid & 31;
    const int bh   = blockIdx.y;
    const int b    = bh / NH;
    const int h    = bh - b * NH;
    const int qb   = blockIdx.x * 128;

    const float* Qg = g_q + (size_t)bh * SEQ * HD;
    const float* Kg = g_k + (size_t)bh * SEQ * HD;
    const float* Vg = g_v + (size_t)bh * SEQ * HD;
    float*       Yg = g_y + (size_t)bh * SEQ * HD;

    float bs;
    {
        int iv = bsp[0];
        bs = (iv > -1000000 && iv < 1000000) ? (float)iv : __int_as_float(iv);
    }
    float G1 = 0.5f * tanhf(mb_raw[h * 3 + 0]) * bs;
    float G2 = 0.5f * tanhf(mb_raw[h * 3 + 1]) * bs;
    float G3 = 0.5f * tanhf(mb_raw[h * 3 + 2]) * bs;
    const float b01 = fminf(2.0f, fmaxf(-2.0f, G2));
    const float b10 = fminf(2.0f, fmaxf(-2.0f, G1));
    const float b11 = fminf(2.0f, fmaxf(-2.0f, G1 + G2 + G3));

    const int rA = qb + w * 16 + (lane >> 2);
    const int cb = (lane & 3) * 2;
    const int miA = tmask[b * SEQ + rA];
    const int miB = tmask[b * SEQ + rA + 8];
    const float bm0A = (miA ? b10 : 0.0f) - 4.0f;
    const float bm1A = (miA ? b11 : b01 ) - 4.0f;
    const float bm0B = (miB ? b10 : 0.0f) - 4.0f;
    const float bm1B = (miB ? b11 : b01 ) - 4.0f;

    // Q fragments (hi + lo) in registers
    uint32_t qhi[16], qlo[16];
    {
        const float* qA = Qg + (size_t)rA * HD + cb;
        const float* qB = qA + 8 * HD;
        #pragma unroll
        for (int kc = 0; kc < 4; kc++) {
            float2 fA0 = *(const float2*)(qA + kc * 16);
            float2 fB0 = *(const float2*)(qB + kc * 16);
            float2 fA1 = *(const float2*)(qA + kc * 16 + 8);
            float2 fB1 = *(const float2*)(qB + kc * 16 + 8);
            qhi[kc*4+0] = pack_h2(fA0.x, fA0.y);
            qhi[kc*4+1] = pack_h2(fB0.x, fB0.y);
            qhi[kc*4+2] = pack_h2(fA1.x, fA1.y);
            qhi[kc*4+3] = pack_h2(fB1.x, fB1.y);
            qlo[kc*4+0] = pack_h2(lo_res(fA0.x), lo_res(fA0.y));
            qlo[kc*4+1] = pack_h2(lo_res(fB0.x), lo_res(fB0.y));
            qlo[kc*4+2] = pack_h2(lo_res(fA1.x), lo_res(fA1.y));
            qlo[kc*4+3] = pack_h2(lo_res(fB1.x), lo_res(fB1.y));
        }
    }

    const int joK = (lane & 7) + ((lane >> 4) & 1) * 8;
    const int doK = ((lane >> 3) & 1) * 8;
    const uint32_t lK = (uint32_t)(joK * 128 + doK * 2);
    const uint32_t xK = (uint32_t)((joK & 7) << 4);
    const int joV = (lane & 7) + ((lane >> 3) & 1) * 8;
    const int doV = ((lane >> 4) & 1) * 8;
    const uint32_t lV = (uint32_t)(joV * 128 + doV * 2);
    const uint32_t xV = (uint32_t)((joV & 7) << 4);

    const uint32_t khiA = smem_u32(Khi);
    const uint32_t kloA = smem_u32(Klo);
    const uint32_t vhiA = smem_u32(Vhi);

    float o[8][4];
    #pragma unroll
    for (int i = 0; i < 8; i++)
        #pragma unroll
        for (int jx = 0; jx < 4; jx++) o[i][jx] = 0.0f;
    float lA = 0.0f, lB = 0.0f;

    const int jc = tid >> 2;
    const int dg = tid & 3;
    const uint32_t coff = (uint32_t)(jc * 128 + dg * 32);
    const uint32_t cxor = (uint32_t)((jc & 7) << 4);

    for (int kt = 0; kt < SEQ / 64; kt++) {
        __syncthreads();
        // ---- convert K (hi+lo) and V (hi) tiles to fp16 smem ----
        {
            const float* kr = Kg + ((size_t)(kt * 64 + jc)) * HD + dg * 16;
            float4 f0 = *(const float4*)(kr + 0);
            float4 f1 = *(const float4*)(kr + 4);
            float4 f2 = *(const float4*)(kr + 8);
            float4 f3 = *(const float4*)(kr + 12);
            uint4 h0, h1, l0, l1;
            h0.x = pack_h2(f0.x, f0.y); h0.y = pack_h2(f0.z, f0.w);
            h0.z = pack_h2(f1.x, f1.y); h0.w = pack_h2(f1.z, f1.w);
            h1.x = pack_h2(f2.x, f2.y); h1.y = pack_h2(f2.z, f2.w);
            h1.z = pack_h2(f3.x, f3.y); h1.w = pack_h2(f3.z, f3.w);
            l0.x = pack_h2(lo_res(f0.x), lo_res(f0.y)); l0.y = pack_h2(lo_res(f0.z), lo_res(f0.w));
            l0.z = pack_h2(lo_res(f1.x), lo_res(f1.y)); l0.w = pack_h2(lo_res(f1.z), lo_res(f1.w));
            l1.x = pack_h2(lo_res(f2.x), lo_res(f2.y)); l1.y = pack_h2(lo_res(f2.z), lo_res(f2.w));
            l1.z = pack_h2(lo_res(f3.x), lo_res(f3.y)); l1.w = pack_h2(lo_res(f3.z), lo_res(f3.w));
            *(uint4*)(Khi + ( coff       ^ cxor)) = h0;
            *(uint4*)(Khi + ((coff + 16) ^ cxor)) = h1;
            *(uint4*)(Klo + ( coff       ^ cxor)) = l0;
            *(uint4*)(Klo + ((coff + 16) ^ cxor)) = l1;

            const float* vr = Vg + ((size_t)(kt * 64 + jc)) * HD + dg * 16;
            float4 g0 = *(const float4*)(vr + 0);
            float4 g1 = *(const float4*)(vr + 4);
            float4 g2 = *(const float4*)(vr + 8);
            float4 g3 = *(const float4*)(vr + 12);
            uint4 v0, v1;
            v0.x = pack_h2(g0.x, g0.y); v0.y = pack_h2(g0.z, g0.w);
            v0.z = pack_h2(g1.x, g1.y); v0.w = pack_h2(g1.z, g1.w);
            v1.x = pack_h2(g2.x, g2.y); v1.y = pack_h2(g2.z, g2.w);
            v1.z = pack_h2(g3.x, g3.y); v1.w = pack_h2(g3.z, g3.w);
            *(uint4*)(Vhi + ( coff       ^ cxor)) = v0;
            *(uint4*)(Vhi + ((coff + 16) ^ cxor)) = v1;

            if (tid < 64) s_mj[tid] = tmask[b * SEQ + kt * 64 + tid];
        }
        __syncthreads();

        // ---- two 32-col halves: QK -> softmax -> PV ----
        #pragma unroll
        for (int half = 0; half < 2; half++) {
            float sf[4][4];
            #pragma unroll
            for (int i = 0; i < 4; i++)
                #pragma unroll
                for (int jx = 0; jx < 4; jx++) sf[i][jx] = 0.0f;

            #pragma unroll
            for (int nb2 = 0; nb2 < 2; nb2++) {
                #pragma unroll
                for (int kc = 0; kc < 4; kc++) {
                    uint32_t off = (uint32_t)((half * 2 + nb2) * 2048 + kc * 32) + lK;
                    uint32_t bh0, bh1, bh2, bh3;
                    ldsm_x4(bh0, bh1, bh2, bh3, (khiA + off) ^ xK);
                    mma16816(sf[2*nb2],   qhi[kc*4+0], qhi[kc*4+1], qhi[kc*4+2], qhi[kc*4+3], bh0, bh1);
                    mma16816(sf[2*nb2+1], qhi[kc*4+0], qhi[kc*4+1], qhi[kc*4+2], qhi[kc*4+3], bh2, bh3);
                    mma16816(sf[2*nb2],   qlo[kc*4+0], qlo[kc*4+1], qlo[kc*4+2], qlo[kc*4+3], bh0, bh1);
                    mma16816(sf[2*nb2+1], qlo[kc*4+0], qlo[kc*4+1], qlo[kc*4+2], qlo[kc*4+3], bh2, bh3);
                    uint32_t bl0, bl1, bl2, bl3;
                    ldsm_x4(bl0, bl1, bl2, bl3, (kloA + off) ^ xK);
                    mma16816(sf[2*nb2],   qhi[kc*4+0], qhi[kc*4+1], qhi[kc*4+2], qhi[kc*4+3], bl0, bl1);
                    mma16816(sf[2*nb2+1], qhi[kc*4+0], qhi[kc*4+1], qhi[kc*4+2], qhi[kc*4+3], bl2, bl3);
                }
            }

            // softmax: p = exp(s*0.125 + bias - 4)
            uint32_t phi[8], plo[8];
            #pragma unroll
            for (int nb = 0; nb < 4; nb++) {
                int j0 = half * 32 + nb * 8 + cb;
                int mj0 = s_mj[j0], mj1 = s_mj[j0 + 1];
                float bA0 = mj0 ? bm1A : bm0A;
                float bA1 = mj1 ? bm1A : bm0A;
                float bB0 = mj0 ? bm1B : bm0B;
                float bB1 = mj1 ? bm1B : bm0B;
                float pA0 = __expf(fmaf(sf[nb][0], 0.125f, bA0));
                float pA1 = __expf(fmaf(sf[nb][1], 0.125f, bA1));
                float pB0 = __expf(fmaf(sf[nb][2], 0.125f, bB0));
                float pB1 = __expf(fmaf(sf[nb][3], 0.125f, bB1));
                lA += pA0 + pA1;
                lB += pB0 + pB1;
                phi[nb*2+0] = pack_h2(pA0, pA1);
                phi[nb*2+1] = pack_h2(pB0, pB1);
                plo[nb*2+0] = pack_h2(lo_res(pA0), lo_res(pA1));
                plo[nb*2+1] = pack_h2(lo_res(pB0), lo_res(pB1));
            }

            // O += P V over this half's 32 j's
            #pragma unroll
            for (int db2 = 0; db2 < 4; db2++) {
                #pragma unroll
                for (int kc = 0; kc < 2; kc++) {
                    uint32_t off = (uint32_t)((half * 2 + kc) * 2048 + db2 * 32) + lV;
                    uint32_t v0, v1, v2, v3;
                    ldsm_x4_t(v0, v1, v2, v3, (vhiA + off) ^ xV);
                    mma16816(o[2*db2],   phi[4*kc+0], phi[4*kc+1], phi[4*kc+2], phi[4*kc+3], v0, v1);
                    mma16816(o[2*db2+1], phi[4*kc+0], phi[4*kc+1], phi[4*kc+2], phi[4*kc+3], v2, v3);
                    mma16816(o[2*db2],   plo[4*kc+0], plo[4*kc+1], plo[4*kc+2], plo[4*kc+3], v0, v1);
                    mma16816(o[2*db2+1], plo[4*kc+0], plo[4*kc+1], plo[4*kc+2], plo[4*kc+3], v2, v3);
                }
            }
        }
    }

    // ---- epilogue ----
    lA += __shfl_xor_sync(0xffffffffu, lA, 1);
    lA += __shfl_xor_sync(0xffffffffu, lA, 2);
    lB += __shfl_xor_sync(0xffffffffu, lB, 1);
    lB += __shfl_xor_sync(0xffffffffu, lB, 2);
    float iA = 1.0f / lA, iB = 1.0f / lB;

    float* yA = Yg + (size_t)rA * HD + cb;
    float* yB = yA + 8 * HD;
    #pragma unroll
    for (int db = 0; db < 8; db++) {
        *(float2*)(yA + db * 8) = make_float2(o[db][0] * iA, o[db][1] * iA);
        *(float2*)(yB + db * 8) = make_float2(o[db][2] * iB, o[db][3] * iB);
    }
}

// ---------------------------------------------------------------------------
extern "C" void kernel_launch(void* const* d_in, const int* in_sizes, int n_in,
                              void* d_out, int out_size)
{
    const float* x    = (const float*)d_in[0];
    const float* cosp = (const float*)d_in[1];
    const float* sinp = (const float*)d_in[2];
    const int*   tmsk = (const int*)  d_in[3];
    const float* Wq   = (const float*)d_in[4];
    const float* Wk   = (const float*)d_in[5];
    const float* Wv   = (const float*)d_in[6];
    const float* Wpr  = (const float*)d_in[7];
    const float* mbr  = (const float*)d_in[8];
    const int*   bsp  = (const int*)  d_in[9];
    float* out = (float*)d_out;

    dim3 gg(BATCH * SEQ / 128, NH);   // 64 x 6
    gemm_tc<0, 0, true ><<<gg, 256>>>(x, Wq, cosp, sinp, nullptr);
    gemm_tc<0, 1, true ><<<gg, 256>>>(x, Wk, cosp, sinp, nullptr);
    gemm_tc<0, 2, false><<<gg, 256>>>(x, Wv, nullptr, nullptr, nullptr);

    attn_kernel<<<dim3(SEQ / 128, BATCH * NH), 256>>>(tmsk, mbr, bsp);

    gemm_tc<1, 3, false><<<gg, 256>>>(nullptr, Wpr, nullptr, nullptr, out);
}

// round 6
// speedup vs baseline: 3.5508x; 1.1967x over previous
#include <cuda_runtime.h>
#include <cuda_fp16.h>
#include <math.h>
#include <stdint.h>

#define BATCH 4
#define SEQ   2048
#define CDIM  384
#define NH    6
#define HD    64
#define NT    (SEQ / 64)          // 32 KV tiles per (b,h)

// Scratch (static __device__ arrays — no runtime allocation allowed).
__device__ float g_q[BATCH*NH*SEQ*HD];
__device__ float g_y[BATCH*NH*SEQ*HD];
// Pre-swizzled fp16 tile images: [bh][tile][8192 bytes] (ldmatrix-ready).
__device__ uint4 g_kh[BATCH*NH*NT*512];
__device__ uint4 g_kl[BATCH*NH*NT*512];
__device__ uint4 g_vh[BATCH*NH*NT*512];

// ---------------------------------------------------------------------------
// helpers (sm_80-compatible PTX; assembles for sm_100)
// ---------------------------------------------------------------------------
__device__ __forceinline__ uint32_t smem_u32(const void* p) {
    uint32_t a;
    asm("{ .reg .u64 t; cvta.to.shared.u64 t, %1; cvt.u32.u64 %0, t; }"
        : "=r"(a) : "l"(p));
    return a;
}
__device__ __forceinline__ void ldsm_x4(uint32_t& r0, uint32_t& r1,
                                        uint32_t& r2, uint32_t& r3, uint32_t addr) {
    asm volatile("ldmatrix.sync.aligned.m8n8.x4.shared.b16 {%0,%1,%2,%3}, [%4];"
                 : "=r"(r0), "=r"(r1), "=r"(r2), "=r"(r3) : "r"(addr));
}
__device__ __forceinline__ void ldsm_x4_t(uint32_t& r0, uint32_t& r1,
                                          uint32_t& r2, uint32_t& r3, uint32_t addr) {
    asm volatile("ldmatrix.sync.aligned.m8n8.x4.trans.shared.b16 {%0,%1,%2,%3}, [%4];"
                 : "=r"(r0), "=r"(r1), "=r"(r2), "=r"(r3) : "r"(addr));
}
__device__ __forceinline__ void mma16816(float* d,
    uint32_t a0, uint32_t a1, uint32_t a2, uint32_t a3, uint32_t b0, uint32_t b1) {
    asm volatile(
        "mma.sync.aligned.m16n8k16.row.col.f32.f16.f16.f32 "
        "{%0,%1,%2,%3}, {%4,%5,%6,%7}, {%8,%9}, {%0,%1,%2,%3};"
        : "+f"(d[0]), "+f"(d[1]), "+f"(d[2]), "+f"(d[3])
        : "r"(a0), "r"(a1), "r"(a2), "r"(a3), "r"(b0), "r"(b1));
}
__device__ __forceinline__ uint32_t pack_h2(float x, float y) {
    __half2 h = __floats2half2_rn(x, y);
    return *reinterpret_cast<uint32_t*>(&h);
}
__device__ __forceinline__ float lo_res(float x) {
    return x - __half2float(__float2half_rn(x));
}
__device__ __forceinline__ uint32_t sw64(uint32_t off) {
    return off ^ ((off >> 3) & 0x30);
}
__device__ __forceinline__ uint32_t sw128(uint32_t off) {
    return off ^ ((off >> 3) & 0x70);
}
__device__ __forceinline__ void cp_async16(uint32_t dst, const void* src) {
    asm volatile("cp.async.cg.shared.global [%0], [%1], 16;" :: "r"(dst), "l"(src));
}
#define CP_COMMIT() asm volatile("cp.async.commit_group;" ::: "memory")
#define CP_WAIT1()  asm volatile("cp.async.wait_group 1;" ::: "memory")
#define CP_WAIT0()  asm volatile("cp.async.wait_group 0;" ::: "memory")

// ===========================================================================
// Tensor-core GEMM: out[r, j] = sum_c A[r, c] * W[j, c]
//   DST 0: g_q fp32 (+ROPE)   DST 1: K -> g_kh/g_kl fp16 pre-swizzled (+ROPE)
//   DST 2: V -> g_vh fp16 pre-swizzled    DST 3: outp [B,T,C]
// ===========================================================================
template<int SRC, int DST, bool ROPE>
__global__ __launch_bounds__(256, 2)
void gemm_tc(const float* __restrict__ A,
             const float* __restrict__ W,
             const float* __restrict__ cosp,
             const float* __restrict__ sinp,
             float* __restrict__ outp)
{
    __shared__ __align__(16) char sAhi[8192];   // [128][32] fp16, 64B rows
    __shared__ __align__(16) char sAlo[8192];
    __shared__ __align__(16) char sWhi[4096];   // [64][32] fp16
    __shared__ __align__(16) char sWlo[4096];

    const int tid  = threadIdx.x;
    const int w    = tid >> 5;
    const int lane = tid & 31;
    const int rbase = blockIdx.x * 128;
    const int jb    = blockIdx.y * 64;

    const uint32_t aHi = smem_u32(sAhi);
    const uint32_t aLo = smem_u32(sAlo);
    const uint32_t wHi = smem_u32(sWhi);
    const uint32_t wLo = smem_u32(sWlo);

    float acc[8][4];
    #pragma unroll
    for (int m = 0; m < 8; m++)
        #pragma unroll
        for (int i = 0; i < 4; i++) acc[m][i] = 0.0f;

    const uint32_t aoff = (uint32_t)((w * 16 + (lane & 15)) * 64 + ((lane >> 4) & 1) * 16);
    const int joK = (lane & 7) + ((lane >> 4) & 1) * 8;
    const int doK = ((lane >> 3) & 1) * 8;

    const int rl = tid >> 1;
    const int ko = (tid & 1) * 16;
    const int rw = tid >> 2;
    const int kw = (tid & 3) * 8;

    for (int kb = 0; kb < CDIM; kb += 32) {
        __syncthreads();
        {
            const float* src;
            int rg = rbase + rl;
            if (SRC == 1) {
                int bb = rg >> 11, t = rg & (SEQ - 1);
                int c0 = kb + ko;
                src = g_y + ((size_t)(bb * NH + (c0 >> 6)) * SEQ + t) * HD + (c0 & 63);
            } else {
                src = A + (size_t)rg * CDIM + kb + ko;
            }
            float4 f0 = *(const float4*)(src + 0);
            float4 f1 = *(const float4*)(src + 4);
            float4 f2 = *(const float4*)(src + 8);
            float4 f3 = *(const float4*)(src + 12);
            uint4 h0, h1, l0, l1;
            h0.x = pack_h2(f0.x, f0.y); h0.y = pack_h2(f0.z, f0.w);
            h0.z = pack_h2(f1.x, f1.y); h0.w = pack_h2(f1.z, f1.w);
            h1.x = pack_h2(f2.x, f2.y); h1.y = pack_h2(f2.z, f2.w);
            h1.z = pack_h2(f3.x, f3.y); h1.w = pack_h2(f3.z, f3.w);
            l0.x = pack_h2(lo_res(f0.x), lo_res(f0.y)); l0.y = pack_h2(lo_res(f0.z), lo_res(f0.w));
            l0.z = pack_h2(lo_res(f1.x), lo_res(f1.y)); l0.w = pack_h2(lo_res(f1.z), lo_res(f1.w));
            l1.x = pack_h2(lo_res(f2.x), lo_res(f2.y)); l1.y = pack_h2(lo_res(f2.z), lo_res(f2.w));
            l1.z = pack_h2(lo_res(f3.x), lo_res(f3.y)); l1.w = pack_h2(lo_res(f3.z), lo_res(f3.w));
            uint32_t g = (uint32_t)(rl * 64 + ko * 2);
            *(uint4*)(sAhi + sw64(g))      = h0;
            *(uint4*)(sAhi + sw64(g + 16)) = h1;
            *(uint4*)(sAlo + sw64(g))      = l0;
            *(uint4*)(sAlo + sw64(g + 16)) = l1;
        }
        {
            const float* src = W + (size_t)(jb + rw) * CDIM + kb + kw;
            float4 f0 = *(const float4*)(src + 0);
            float4 f1 = *(const float4*)(src + 4);
            uint4 hh, ll;
            hh.x = pack_h2(f0.x, f0.y); hh.y = pack_h2(f0.z, f0.w);
            hh.z = pack_h2(f1.x, f1.y); hh.w = pack_h2(f1.z, f1.w);
            ll.x = pack_h2(lo_res(f0.x), lo_res(f0.y)); ll.y = pack_h2(lo_res(f0.z), lo_res(f0.w));
            ll.z = pack_h2(lo_res(f1.x), lo_res(f1.y)); ll.w = pack_h2(lo_res(f1.z), lo_res(f1.w));
            uint32_t g = (uint32_t)(rw * 64 + kw * 2);
            *(uint4*)(sWhi + sw64(g)) = hh;
            *(uint4*)(sWlo + sw64(g)) = ll;
        }
        __syncthreads();

        #pragma unroll
        for (int kc = 0; kc < 2; kc++) {
            uint32_t ah0, ah1, ah2, ah3, al0, al1, al2, al3;
            ldsm_x4(ah0, ah1, ah2, ah3, aHi + sw64(aoff + kc * 32));
            ldsm_x4(al0, al1, al2, al3, aLo + sw64(aoff + kc * 32));
            #pragma unroll
            for (int cg = 0; cg < 4; cg++) {
                uint32_t boff = sw64((uint32_t)((cg * 16 + joK) * 64 + kc * 32 + doK * 2));
                uint32_t bh0, bh1, bh2, bh3;
                ldsm_x4(bh0, bh1, bh2, bh3, wHi + boff);
                mma16816(acc[2*cg],   ah0, ah1, ah2, ah3, bh0, bh1);
                mma16816(acc[2*cg+1], ah0, ah1, ah2, ah3, bh2, bh3);
                mma16816(acc[2*cg],   al0, al1, al2, al3, bh0, bh1);
                mma16816(acc[2*cg+1], al0, al1, al2, al3, bh2, bh3);
                uint32_t bl0, bl1, bl2, bl3;
                ldsm_x4(bl0, bl1, bl2, bl3, wLo + boff);
                mma16816(acc[2*cg],   ah0, ah1, ah2, ah3, bl0, bl1);
                mma16816(acc[2*cg+1], ah0, ah1, ah2, ah3, bl2, bl3);
            }
        }
    }

    // ---- epilogue ----
    const int rA = rbase + w * 16 + (lane >> 2);
    const int cb = (lane & 3) * 2;

    #pragma unroll
    for (int rp = 0; rp < 2; rp++) {
        int r = rA + rp * 8;
        int i0 = rp * 2;
        if (ROPE) {
            int t = r & (SEQ - 1);
            #pragma unroll
            for (int m = 0; m < 4; m++) {
                int d0 = (m >> 1) * 16 + (m & 1) * 8 + cb;
                float c0 = cosp[t * 32 + d0],     s0 = sinp[t * 32 + d0];
                float c1 = cosp[t * 32 + d0 + 1], s1 = sinp[t * 32 + d0 + 1];
                float x1 = acc[m][i0],     x2 = acc[m+4][i0];
                acc[m][i0]     =  x1 * c0 + x2 * s0;
                acc[m+4][i0]   = -x1 * s0 + x2 * c0;
                float y1 = acc[m][i0+1],   y2 = acc[m+4][i0+1];
                acc[m][i0+1]   =  y1 * c1 + y2 * s1;
                acc[m+4][i0+1] = -y1 * s1 + y2 * c1;
            }
            float ss = 0.0f;
            #pragma unroll
            for (int m = 0; m < 8; m++)
                ss += acc[m][i0]*acc[m][i0] + acc[m][i0+1]*acc[m][i0+1];
            ss += __shfl_xor_sync(0xffffffffu, ss, 1);
            ss += __shfl_xor_sync(0xffffffffu, ss, 2);
            float rn = rsqrtf(ss * (1.0f / HD) + 1.1920929e-07f);
            #pragma unroll
            for (int m = 0; m < 8; m++) { acc[m][i0] *= rn; acc[m][i0+1] *= rn; }
        }
        if (DST == 3) {
            float* o = outp + (size_t)r * CDIM + jb;
            #pragma unroll
            for (int m = 0; m < 8; m++) {
                int d0 = (m >> 1) * 16 + (m & 1) * 8 + cb;
                *(float2*)(o + d0) = make_float2(acc[m][i0], acc[m][i0+1]);
            }
        } else if (DST == 0) {
            int bb = r >> 11, t = r & (SEQ - 1);
            float* o = g_q + ((size_t)(bb * NH + blockIdx.y) * SEQ + t) * HD;
            #pragma unroll
            for (int m = 0; m < 8; m++) {
                int d0 = (m >> 1) * 16 + (m & 1) * 8 + cb;
                *(float2*)(o + d0) = make_float2(acc[m][i0], acc[m][i0+1]);
            }
        } else {
            // K/V: write fp16 pre-swizzled tile images
            int bb = r >> 11, t = r & (SEQ - 1);
            int bh = bb * NH + blockIdx.y;
            int tile = t >> 6, j = t & 63;
            size_t base = ((size_t)(bh * NT + tile)) * 8192;
            char* dh = (char*)(DST == 1 ? g_kh : g_vh) + base;
            char* dl = (char*)g_kl + base;
            #pragma unroll
            for (int m = 0; m < 8; m++) {
                int d0 = (m >> 1) * 16 + (m & 1) * 8 + cb;
                uint32_t off = sw128((uint32_t)(j * 128 + d0 * 2));
                *(uint32_t*)(dh + off) = pack_h2(acc[m][i0], acc[m][i0+1]);
                if (DST == 1)
                    *(uint32_t*)(dl + off) = pack_h2(lo_res(acc[m][i0]), lo_res(acc[m][i0+1]));
            }
        }
    }
}

// ===========================================================================
// Tensor-core flash attention: cp.async double-buffered fp16 tiles.
//   Stage layout (24832 B): Khi[8192] Klo[8192] Vhi[8192] mask[256]
// ===========================================================================
#define STAGE_SZ 24832

__global__ __launch_bounds__(256, 2)
void attn_kernel(const int* __restrict__ tmask,
                 const float* __restrict__ mb_raw,
                 const int* __restrict__ bsp)
{
    extern __shared__ __align__(16) char s_dyn[];

    const int tid  = threadIdx.x;
    const int w    = tid >> 5;
    const int lane = tid & 31;
    const int bh   = blockIdx.y;
    const int b    = bh / NH;
    const int h    = bh - b * NH;
    const int qb   = blockIdx.x * 128;

    const float* Qg = g_q + (size_t)bh * SEQ * HD;
    float*       Yg = g_y + (size_t)bh * SEQ * HD;
    const char*  KH = (const char*)g_kh + (size_t)bh * NT * 8192;
    const char*  KL = (const char*)g_kl + (size_t)bh * NT * 8192;
    const char*  VH = (const char*)g_vh + (size_t)bh * NT * 8192;
    const int*   MK = tmask + b * SEQ;

    const uint32_t sb0 = smem_u32(s_dyn);

    float bs;
    {
        int iv = bsp[0];
        bs = (iv > -1000000 && iv < 1000000) ? (float)iv : __int_as_float(iv);
    }
    float G1 = 0.5f * tanhf(mb_raw[h * 3 + 0]) * bs;
    float G2 = 0.5f * tanhf(mb_raw[h * 3 + 1]) * bs;
    float G3 = 0.5f * tanhf(mb_raw[h * 3 + 2]) * bs;
    const float b01 = fminf(2.0f, fmaxf(-2.0f, G2));
    const float b10 = fminf(2.0f, fmaxf(-2.0f, G1));
    const float b11 = fminf(2.0f, fmaxf(-2.0f, G1 + G2 + G3));

    const int rA = qb + w * 16 + (lane >> 2);
    const int cb = (lane & 3) * 2;
    const int miA = MK[rA];
    const int miB = MK[rA + 8];
    const float bm0A = (miA ? b10 : 0.0f) - 4.0f;
    const float bm1A = (miA ? b11 : b01 ) - 4.0f;
    const float bm0B = (miB ? b10 : 0.0f) - 4.0f;
    const float bm1B = (miB ? b11 : b01 ) - 4.0f;

    // Q fragments (hi + lo) in registers
    uint32_t qhi[16], qlo[16];
    {
        const float* qA = Qg + (size_t)rA * HD + cb;
        const float* qB = qA + 8 * HD;
        #pragma unroll
        for (int kc = 0; kc < 4; kc++) {
            float2 fA0 = *(const float2*)(qA + kc * 16);
            float2 fB0 = *(const float2*)(qB + kc * 16);
            float2 fA1 = *(const float2*)(qA + kc * 16 + 8);
            float2 fB1 = *(const float2*)(qB + kc * 16 + 8);
            qhi[kc*4+0] = pack_h2(fA0.x, fA0.y);
            qhi[kc*4+1] = pack_h2(fB0.x, fB0.y);
            qhi[kc*4+2] = pack_h2(fA1.x, fA1.y);
            qhi[kc*4+3] = pack_h2(fB1.x, fB1.y);
            qlo[kc*4+0] = pack_h2(lo_res(fA0.x), lo_res(fA0.y));
            qlo[kc*4+1] = pack_h2(lo_res(fB0.x), lo_res(fB0.y));
            qlo[kc*4+2] = pack_h2(lo_res(fA1.x), lo_res(fA1.y));
            qlo[kc*4+3] = pack_h2(lo_res(fB1.x), lo_res(fB1.y));
        }
    }

    const int joK = (lane & 7) + ((lane >> 4) & 1) * 8;
    const int doK = ((lane >> 3) & 1) * 8;
    const uint32_t lK = (uint32_t)(joK * 128 + doK * 2);
    const uint32_t xK = (uint32_t)((joK & 7) << 4);
    const int joV = (lane & 7) + ((lane >> 3) & 1) * 8;
    const int doV = ((lane >> 4) & 1) * 8;
    const uint32_t lV = (uint32_t)(joV * 128 + doV * 2);
    const uint32_t xV = (uint32_t)((joV & 7) << 4);

    float o[8][4];
    #pragma unroll
    for (int i = 0; i < 8; i++)
        #pragma unroll
        for (int jx = 0; jx < 4; jx++) o[i][jx] = 0.0f;
    float lA = 0.0f, lB = 0.0f;

    // ---- prefetch tile 0 ----
    {
        uint32_t sb = sb0;
        const char* kh = KH;  const char* kl = KL;  const char* vh = VH;
        #pragma unroll
        for (int i = 0; i < 2; i++) {
            uint32_t c = (uint32_t)(tid + i * 256) * 16;
            cp_async16(sb + c,         kh + c);
            cp_async16(sb + 8192 + c,  kl + c);
            cp_async16(sb + 16384 + c, vh + c);
        }
        if (tid < 16) cp_async16(sb + 24576 + tid * 16, MK + tid * 4);
        CP_COMMIT();
    }

    for (int kt = 0; kt < NT; kt++) {
        const int s = kt & 1;
        if (kt + 1 < NT) {
            uint32_t sb = sb0 + (s ^ 1) * STAGE_SZ;
            size_t toff = (size_t)(kt + 1) * 8192;
            const char* kh = KH + toff;
            const char* kl = KL + toff;
            const char* vh = VH + toff;
            #pragma unroll
            for (int i = 0; i < 2; i++) {
                uint32_t c = (uint32_t)(tid + i * 256) * 16;
                cp_async16(sb + c,         kh + c);
                cp_async16(sb + 8192 + c,  kl + c);
                cp_async16(sb + 16384 + c, vh + c);
            }
            if (tid < 16) cp_async16(sb + 24576 + tid * 16, MK + (kt + 1) * 64 + tid * 4);
            CP_COMMIT();
            CP_WAIT1();
        } else {
            CP_WAIT0();
        }
        __syncthreads();

        const uint32_t khiA = sb0 + s * STAGE_SZ;
        const uint32_t kloA = khiA + 8192;
        const uint32_t vhiA = khiA + 16384;
        const int* mjs = (const int*)(s_dyn + s * STAGE_SZ + 24576);

        #pragma unroll
        for (int half = 0; half < 2; half++) {
            float sf[4][4];
            #pragma unroll
            for (int i = 0; i < 4; i++)
                #pragma unroll
                for (int jx = 0; jx < 4; jx++) sf[i][jx] = 0.0f;

            #pragma unroll
            for (int nb2 = 0; nb2 < 2; nb2++) {
                #pragma unroll
                for (int kc = 0; kc < 4; kc++) {
                    uint32_t off = (uint32_t)((half * 2 + nb2) * 2048 + kc * 32) + lK;
                    uint32_t bh0, bh1, bh2, bh3;
                    ldsm_x4(bh0, bh1, bh2, bh3, (khiA + off) ^ xK);
                    mma16816(sf[2*nb2],   qhi[kc*4+0], qhi[kc*4+1], qhi[kc*4+2], qhi[kc*4+3], bh0, bh1);
                    mma16816(sf[2*nb2+1], qhi[kc*4+0], qhi[kc*4+1], qhi[kc*4+2], qhi[kc*4+3], bh2, bh3);
                    mma16816(sf[2*nb2],   qlo[kc*4+0], qlo[kc*4+1], qlo[kc*4+2], qlo[kc*4+3], bh0, bh1);
                    mma16816(sf[2*nb2+1], qlo[kc*4+0], qlo[kc*4+1], qlo[kc*4+2], qlo[kc*4+3], bh2, bh3);
                    uint32_t bl0, bl1, bl2, bl3;
                    ldsm_x4(bl0, bl1, bl2, bl3, (kloA + off) ^ xK);
                    mma16816(sf[2*nb2],   qhi[kc*4+0], qhi[kc*4+1], qhi[kc*4+2], qhi[kc*4+3], bl0, bl1);
                    mma16816(sf[2*nb2+1], qhi[kc*4+0], qhi[kc*4+1], qhi[kc*4+2], qhi[kc*4+3], bl2, bl3);
                }
            }

            uint32_t phi[8], plo[8];
            #pragma unroll
            for (int nb = 0; nb < 4; nb++) {
                int j0 = half * 32 + nb * 8 + cb;
                int mj0 = mjs[j0], mj1 = mjs[j0 + 1];
                float bA0 = mj0 ? bm1A : bm0A;
                float bA1 = mj1 ? bm1A : bm0A;
                float bB0 = mj0 ? bm1B : bm0B;
                float bB1 = mj1 ? bm1B : bm0B;
                float pA0 = __expf(fmaf(sf[nb][0], 0.125f, bA0));
                float pA1 = __expf(fmaf(sf[nb][1], 0.125f, bA1));
                float pB0 = __expf(fmaf(sf[nb][2], 0.125f, bB0));
                float pB1 = __expf(fmaf(sf[nb][3], 0.125f, bB1));
                lA += pA0 + pA1;
                lB += pB0 + pB1;
                phi[nb*2+0] = pack_h2(pA0, pA1);
                phi[nb*2+1] = pack_h2(pB0, pB1);
                plo[nb*2+0] = pack_h2(lo_res(pA0), lo_res(pA1));
                plo[nb*2+1] = pack_h2(lo_res(pB0), lo_res(pB1));
            }

            #pragma unroll
            for (int db2 = 0; db2 < 4; db2++) {
                #pragma unroll
                for (int kc = 0; kc < 2; kc++) {
                    uint32_t off = (uint32_t)((half * 2 + kc) * 2048 + db2 * 32) + lV;
                    uint32_t v0, v1, v2, v3;
                    ldsm_x4_t(v0, v1, v2, v3, (vhiA + off) ^ xV);
                    mma16816(o[2*db2],   phi[4*kc+0], phi[4*kc+1], phi[4*kc+2], phi[4*kc+3], v0, v1);
                    mma16816(o[2*db2+1], phi[4*kc+0], phi[4*kc+1], phi[4*kc+2], phi[4*kc+3], v2, v3);
                    mma16816(o[2*db2],   plo[4*kc+0], plo[4*kc+1], plo[4*kc+2], plo[4*kc+3], v0, v1);
                    mma16816(o[2*db2+1], plo[4*kc+0], plo[4*kc+1], plo[4*kc+2], plo[4*kc+3], v2, v3);
                }
            }
        }
        __syncthreads();
    }

    // ---- epilogue ----
    lA += __shfl_xor_sync(0xffffffffu, lA, 1);
    lA += __shfl_xor_sync(0xffffffffu, lA, 2);
    lB += __shfl_xor_sync(0xffffffffu, lB, 1);
    lB += __shfl_xor_sync(0xffffffffu, lB, 2);
    float iA = 1.0f / lA, iB = 1.0f / lB;

    float* yA = Yg + (size_t)rA * HD + cb;
    float* yB = yA + 8 * HD;
    #pragma unroll
    for (int db = 0; db < 8; db++) {
        *(float2*)(yA + db * 8) = make_float2(o[db][0] * iA, o[db][1] * iA);
        *(float2*)(yB + db * 8) = make_float2(o[db][2] * iB, o[db][3] * iB);
    }
}

// ---------------------------------------------------------------------------
extern "C" void kernel_launch(void* const* d_in, const int* in_sizes, int n_in,
                              void* d_out, int out_size)
{
    const float* x    = (const float*)d_in[0];
    const float* cosp = (const float*)d_in[1];
    const float* sinp = (const float*)d_in[2];
    const int*   tmsk = (const int*)  d_in[3];
    const float* Wq   = (const float*)d_in[4];
    const float* Wk   = (const float*)d_in[5];
    const float* Wv   = (const float*)d_in[6];
    const float* Wpr  = (const float*)d_in[7];
    const float* mbr  = (const float*)d_in[8];
    const int*   bsp  = (const int*)  d_in[9];
    float* out = (float*)d_out;

    cudaFuncSetAttribute(attn_kernel,
                         cudaFuncAttributeMaxDynamicSharedMemorySize, 2 * STAGE_SZ);

    dim3 gg(BATCH * SEQ / 128, NH);   // 64 x 6
    gemm_tc<0, 0, true ><<<gg, 256>>>(x, Wq, cosp, sinp, nullptr);
    gemm_tc<0, 1, true ><<<gg, 256>>>(x, Wk, cosp, sinp, nullptr);
    gemm_tc<0, 2, false><<<gg, 256>>>(x, Wv, nullptr, nullptr, nullptr);

    attn_kernel<<<dim3(SEQ / 128, BATCH * NH), 256, 2 * STAGE_SZ>>>(tmsk, mbr, bsp);

    gemm_tc<1, 3, false><<<gg, 256>>>(nullptr, Wpr, nullptr, nullptr, out);
}

// round 8
// speedup vs baseline: 4.7036x; 1.3247x over previous
#include <cuda_runtime.h>
#include <cuda_fp16.h>
#include <math.h>
#include <stdint.h>

#define BATCH 4
#define SEQ   2048
#define CDIM  384
#define NH    6
#define HD    64
#define NT    (SEQ / 64)          // 32 KV tiles per (b,h)

// Scratch (static __device__ arrays — no runtime allocation allowed).
__device__ float g_q[BATCH*NH*SEQ*HD];
__device__ float g_y[BATCH*NH*SEQ*HD];
// Pre-swizzled fp16 tile images: [bh][tile][8192 bytes] (ldmatrix-ready).
__device__ uint4 g_kh[BATCH*NH*NT*512];
__device__ uint4 g_vh[BATCH*NH*NT*512];

// ---------------------------------------------------------------------------
// helpers (sm_80-compatible PTX; assembles for sm_100)
// ---------------------------------------------------------------------------
__device__ __forceinline__ uint32_t smem_u32(const void* p) {
    uint32_t a;
    asm("{ .reg .u64 t; cvta.to.shared.u64 t, %1; cvt.u32.u64 %0, t; }"
        : "=r"(a) : "l"(p));
    return a;
}
__device__ __forceinline__ void ldsm_x4(uint32_t& r0, uint32_t& r1,
                                        uint32_t& r2, uint32_t& r3, uint32_t addr) {
    asm volatile("ldmatrix.sync.aligned.m8n8.x4.shared.b16 {%0,%1,%2,%3}, [%4];"
                 : "=r"(r0), "=r"(r1), "=r"(r2), "=r"(r3) : "r"(addr));
}
__device__ __forceinline__ void ldsm_x4_t(uint32_t& r0, uint32_t& r1,
                                          uint32_t& r2, uint32_t& r3, uint32_t addr) {
    asm volatile("ldmatrix.sync.aligned.m8n8.x4.trans.shared.b16 {%0,%1,%2,%3}, [%4];"
                 : "=r"(r0), "=r"(r1), "=r"(r2), "=r"(r3) : "r"(addr));
}
__device__ __forceinline__ void mma16816(float* d,
    uint32_t a0, uint32_t a1, uint32_t a2, uint32_t a3, uint32_t b0, uint32_t b1) {
    asm volatile(
        "mma.sync.aligned.m16n8k16.row.col.f32.f16.f16.f32 "
        "{%0,%1,%2,%3}, {%4,%5,%6,%7}, {%8,%9}, {%0,%1,%2,%3};"
        : "+f"(d[0]), "+f"(d[1]), "+f"(d[2]), "+f"(d[3])
        : "r"(a0), "r"(a1), "r"(a2), "r"(a3), "r"(b0), "r"(b1));
}
__device__ __forceinline__ uint32_t pack_h2(float x, float y) {
    __half2 h = __floats2half2_rn(x, y);
    return *reinterpret_cast<uint32_t*>(&h);
}
__device__ __forceinline__ float lo_res(float x) {
    return x - __half2float(__float2half_rn(x));
}
__device__ __forceinline__ uint32_t sw64(uint32_t off) {
    return off ^ ((off >> 3) & 0x30);
}
__device__ __forceinline__ uint32_t sw128(uint32_t off) {
    return off ^ ((off >> 3) & 0x70);
}
__device__ __forceinline__ void cp_async16(uint32_t dst, const void* src) {
    asm volatile("cp.async.cg.shared.global [%0], [%1], 16;" :: "r"(dst), "l"(src));
}
#define CP_COMMIT() asm volatile("cp.async.commit_group;" ::: "memory")
#define CP_WAIT1()  asm volatile("cp.async.wait_group 1;" ::: "memory")
#define CP_WAIT0()  asm volatile("cp.async.wait_group 0;" ::: "memory")

// ===========================================================================
// Tensor-core GEMM: out[r, j] = sum_c A[r, c] * W[j, c]
//   SPLIT = 1: plain fp16 (for q/k — error annihilated by RMSNorm+softmax)
//   SPLIT = 3: hi/lo on both operands (~fp32 accuracy, for v/proj)
//   DST 0: g_q fp32 (+ROPE)  DST 1: K -> g_kh fp16 pre-swizzled (+ROPE)
//   DST 2: V -> g_vh fp16 pre-swizzled   DST 3: outp [B,T,C]
// ===========================================================================
template<int SRC, int DST, bool ROPE, int SPLIT>
__global__ __launch_bounds__(256, 2)
void gemm_tc(const float* __restrict__ A,
             const float* __restrict__ W,
             const float* __restrict__ cosp,
             const float* __restrict__ sinp,
             float* __restrict__ outp)
{
    __shared__ __align__(16) char sAhi[8192];   // [128][32] fp16, 64B rows
    __shared__ __align__(16) char sAlo[8192];
    __shared__ __align__(16) char sWhi[4096];   // [64][32] fp16
    __shared__ __align__(16) char sWlo[4096];

    const int tid  = threadIdx.x;
    const int w    = tid >> 5;
    const int lane = tid & 31;
    const int rbase = blockIdx.x * 128;
    const int jb    = blockIdx.y * 64;

    const uint32_t aHi = smem_u32(sAhi);
    const uint32_t aLo = smem_u32(sAlo);
    const uint32_t wHi = smem_u32(sWhi);
    const uint32_t wLo = smem_u32(sWlo);

    float acc[8][4];
    #pragma unroll
    for (int m = 0; m < 8; m++)
        #pragma unroll
        for (int i = 0; i < 4; i++) acc[m][i] = 0.0f;

    const uint32_t aoff = (uint32_t)((w * 16 + (lane & 15)) * 64 + ((lane >> 4) & 1) * 16);
    const int joK = (lane & 7) + ((lane >> 4) & 1) * 8;
    const int doK = ((lane >> 3) & 1) * 8;

    const int rl = tid >> 1;
    const int ko = (tid & 1) * 16;
    const int rw = tid >> 2;
    const int kw = (tid & 3) * 8;

    for (int kb = 0; kb < CDIM; kb += 32) {
        __syncthreads();
        {
            const float* src;
            int rg = rbase + rl;
            if (SRC == 1) {
                int bb = rg >> 11, t = rg & (SEQ - 1);
                int c0 = kb + ko;
                src = g_y + ((size_t)(bb * NH + (c0 >> 6)) * SEQ + t) * HD + (c0 & 63);
            } else {
                src = A + (size_t)rg * CDIM + kb + ko;
            }
            float4 f0 = *(const float4*)(src + 0);
            float4 f1 = *(const float4*)(src + 4);
            float4 f2 = *(const float4*)(src + 8);
            float4 f3 = *(const float4*)(src + 12);
            uint4 h0, h1;
            h0.x = pack_h2(f0.x, f0.y); h0.y = pack_h2(f0.z, f0.w);
            h0.z = pack_h2(f1.x, f1.y); h0.w = pack_h2(f1.z, f1.w);
            h1.x = pack_h2(f2.x, f2.y); h1.y = pack_h2(f2.z, f2.w);
            h1.z = pack_h2(f3.x, f3.y); h1.w = pack_h2(f3.z, f3.w);
            uint32_t g = (uint32_t)(rl * 64 + ko * 2);
            *(uint4*)(sAhi + sw64(g))      = h0;
            *(uint4*)(sAhi + sw64(g + 16)) = h1;
            if (SPLIT == 3) {
                uint4 l0, l1;
                l0.x = pack_h2(lo_res(f0.x), lo_res(f0.y)); l0.y = pack_h2(lo_res(f0.z), lo_res(f0.w));
                l0.z = pack_h2(lo_res(f1.x), lo_res(f1.y)); l0.w = pack_h2(lo_res(f1.z), lo_res(f1.w));
                l1.x = pack_h2(lo_res(f2.x), lo_res(f2.y)); l1.y = pack_h2(lo_res(f2.z), lo_res(f2.w));
                l1.z = pack_h2(lo_res(f3.x), lo_res(f3.y)); l1.w = pack_h2(lo_res(f3.z), lo_res(f3.w));
                *(uint4*)(sAlo + sw64(g))      = l0;
                *(uint4*)(sAlo + sw64(g + 16)) = l1;
            }
        }
        {
            const float* src = W + (size_t)(jb + rw) * CDIM + kb + kw;
            float4 f0 = *(const float4*)(src + 0);
            float4 f1 = *(const float4*)(src + 4);
            uint4 hh;
            hh.x = pack_h2(f0.x, f0.y); hh.y = pack_h2(f0.z, f0.w);
            hh.z = pack_h2(f1.x, f1.y); hh.w = pack_h2(f1.z, f1.w);
            uint32_t g = (uint32_t)(rw * 64 + kw * 2);
            *(uint4*)(sWhi + sw64(g)) = hh;
            if (SPLIT == 3) {
                uint4 ll;
                ll.x = pack_h2(lo_res(f0.x), lo_res(f0.y)); ll.y = pack_h2(lo_res(f0.z), lo_res(f0.w));
                ll.z = pack_h2(lo_res(f1.x), lo_res(f1.y)); ll.w = pack_h2(lo_res(f1.z), lo_res(f1.w));
                *(uint4*)(sWlo + sw64(g)) = ll;
            }
        }
        __syncthreads();

        #pragma unroll
        for (int kc = 0; kc < 2; kc++) {
            uint32_t ah0, ah1, ah2, ah3;
            ldsm_x4(ah0, ah1, ah2, ah3, aHi + sw64(aoff + kc * 32));
            uint32_t al0, al1, al2, al3;
            if (SPLIT == 3)
                ldsm_x4(al0, al1, al2, al3, aLo + sw64(aoff + kc * 32));
            #pragma unroll
            for (int cg = 0; cg < 4; cg++) {
                uint32_t boff = sw64((uint32_t)((cg * 16 + joK) * 64 + kc * 32 + doK * 2));
                uint32_t bh0, bh1, bh2, bh3;
                ldsm_x4(bh0, bh1, bh2, bh3, wHi + boff);
                mma16816(acc[2*cg],   ah0, ah1, ah2, ah3, bh0, bh1);
                mma16816(acc[2*cg+1], ah0, ah1, ah2, ah3, bh2, bh3);
                if (SPLIT == 3) {
                    mma16816(acc[2*cg],   al0, al1, al2, al3, bh0, bh1);
                    mma16816(acc[2*cg+1], al0, al1, al2, al3, bh2, bh3);
                    uint32_t bl0, bl1, bl2, bl3;
                    ldsm_x4(bl0, bl1, bl2, bl3, wLo + boff);
                    mma16816(acc[2*cg],   ah0, ah1, ah2, ah3, bl0, bl1);
                    mma16816(acc[2*cg+1], ah0, ah1, ah2, ah3, bl2, bl3);
                }
            }
        }
    }

    // ---- epilogue ----
    const int rA = rbase + w * 16 + (lane >> 2);
    const int cb = (lane & 3) * 2;

    #pragma unroll
    for (int rp = 0; rp < 2; rp++) {
        int r = rA + rp * 8;
        int i0 = rp * 2;
        if (ROPE) {
            int t = r & (SEQ - 1);
            #pragma unroll
            for (int m = 0; m < 4; m++) {
                int d0 = (m >> 1) * 16 + (m & 1) * 8 + cb;
                float c0 = cosp[t * 32 + d0],     s0 = sinp[t * 32 + d0];
                float c1 = cosp[t * 32 + d0 + 1], s1 = sinp[t * 32 + d0 + 1];
                float x1 = acc[m][i0],     x2 = acc[m+4][i0];
                acc[m][i0]     =  x1 * c0 + x2 * s0;
                acc[m+4][i0]   = -x1 * s0 + x2 * c0;
                float y1 = acc[m][i0+1],   y2 = acc[m+4][i0+1];
                acc[m][i0+1]   =  y1 * c1 + y2 * s1;
                acc[m+4][i0+1] = -y1 * s1 + y2 * c1;
            }
            float ss = 0.0f;
            #pragma unroll
            for (int m = 0; m < 8; m++)
                ss += acc[m][i0]*acc[m][i0] + acc[m][i0+1]*acc[m][i0+1];
            ss += __shfl_xor_sync(0xffffffffu, ss, 1);
            ss += __shfl_xor_sync(0xffffffffu, ss, 2);
            float rn = rsqrtf(ss * (1.0f / HD) + 1.1920929e-07f);
            #pragma unroll
            for (int m = 0; m < 8; m++) { acc[m][i0] *= rn; acc[m][i0+1] *= rn; }
        }
        if (DST == 3) {
            float* o = outp + (size_t)r * CDIM + jb;
            #pragma unroll
            for (int m = 0; m < 8; m++) {
                int d0 = (m >> 1) * 16 + (m & 1) * 8 + cb;
                *(float2*)(o + d0) = make_float2(acc[m][i0], acc[m][i0+1]);
            }
        } else if (DST == 0) {
            int bb = r >> 11, t = r & (SEQ - 1);
            float* o = g_q + ((size_t)(bb * NH + blockIdx.y) * SEQ + t) * HD;
            #pragma unroll
            for (int m = 0; m < 8; m++) {
                int d0 = (m >> 1) * 16 + (m & 1) * 8 + cb;
                *(float2*)(o + d0) = make_float2(acc[m][i0], acc[m][i0+1]);
            }
        } else {
            // K/V: write fp16 pre-swizzled tile images
            int bb = r >> 11, t = r & (SEQ - 1);
            int bh = bb * NH + blockIdx.y;
            int tile = t >> 6, j = t & 63;
            size_t base = ((size_t)(bh * NT + tile)) * 8192;
            char* dh = (char*)(DST == 1 ? g_kh : g_vh) + base;
            #pragma unroll
            for (int m = 0; m < 8; m++) {
                int d0 = (m >> 1) * 16 + (m & 1) * 8 + cb;
                uint32_t off = sw128((uint32_t)(j * 128 + d0 * 2));
                *(uint32_t*)(dh + off) = pack_h2(acc[m][i0], acc[m][i0+1]);
            }
        }
    }
}

// ===========================================================================
// Tensor-core flash attention: cp.async double-buffered fp16 tiles.
//   QK single fp16 (q/k unit-norm -> exponent error ~5e-5, negligible).
//   PV: P hi/lo + V hi.
//   Stage (16640 B): Khi[8192] Vhi[8192] mask[256]
// ===========================================================================
#define STAGE_SZ 16640

__global__ __launch_bounds__(256, 2)
void attn_kernel(const int* __restrict__ tmask,
                 const float* __restrict__ mb_raw,
                 const int* __restrict__ bsp)
{
    extern __shared__ __align__(16) char s_dyn[];

    const int tid  = threadIdx.x;
    const int w    = tid >> 5;
    const int lane = tid & 31;
    const int bh   = blockIdx.y;
    const int b    = bh / NH;
    const int h    = bh - b * NH;
    const int qb   = blockIdx.x * 128;

    const float* Qg = g_q + (size_t)bh * SEQ * HD;
    float*       Yg = g_y + (size_t)bh * SEQ * HD;
    const char*  KH = (const char*)g_kh + (size_t)bh * NT * 8192;
    const char*  VH = (const char*)g_vh + (size_t)bh * NT * 8192;
    const int*   MK = tmask + b * SEQ;

    const uint32_t sb0 = smem_u32(s_dyn);

    float bs;
    {
        int iv = bsp[0];
        bs = (iv > -1000000 && iv < 1000000) ? (float)iv : __int_as_float(iv);
    }
    float G1 = 0.5f * tanhf(mb_raw[h * 3 + 0]) * bs;
    float G2 = 0.5f * tanhf(mb_raw[h * 3 + 1]) * bs;
    float G3 = 0.5f * tanhf(mb_raw[h * 3 + 2]) * bs;
    const float b01 = fminf(2.0f, fmaxf(-2.0f, G2));
    const float b10 = fminf(2.0f, fmaxf(-2.0f, G1));
    const float b11 = fminf(2.0f, fmaxf(-2.0f, G1 + G2 + G3));

    const int rA = qb + w * 16 + (lane >> 2);
    const int cb = (lane & 3) * 2;
    const int miA = MK[rA];
    const int miB = MK[rA + 8];
    const float bm0A = (miA ? b10 : 0.0f) - 4.0f;
    const float bm1A = (miA ? b11 : b01 ) - 4.0f;
    const float bm0B = (miB ? b10 : 0.0f) - 4.0f;
    const float bm1B = (miB ? b11 : b01 ) - 4.0f;

    // Q fragments (fp16) in registers
    uint32_t qhi[16];
    {
        const float* qA = Qg + (size_t)rA * HD + cb;
        const float* qB = qA + 8 * HD;
        #pragma unroll
        for (int kc = 0; kc < 4; kc++) {
            float2 fA0 = *(const float2*)(qA + kc * 16);
            float2 fB0 = *(const float2*)(qB + kc * 16);
            float2 fA1 = *(const float2*)(qA + kc * 16 + 8);
            float2 fB1 = *(const float2*)(qB + kc * 16 + 8);
            qhi[kc*4+0] = pack_h2(fA0.x, fA0.y);
            qhi[kc*4+1] = pack_h2(fB0.x, fB0.y);
            qhi[kc*4+2] = pack_h2(fA1.x, fA1.y);
            qhi[kc*4+3] = pack_h2(fB1.x, fB1.y);
        }
    }

    const int joK = (lane & 7) + ((lane >> 4) & 1) * 8;
    const int doK = ((lane >> 3) & 1) * 8;
    const uint32_t lK = (uint32_t)(joK * 128 + doK * 2);
    const uint32_t xK = (uint32_t)((joK & 7) << 4);
    const int joV = (lane & 7) + ((lane >> 3) & 1) * 8;
    const int doV = ((lane >> 4) & 1) * 8;
    const uint32_t lV = (uint32_t)(joV * 128 + doV * 2);
    const uint32_t xV = (uint32_t)((joV & 7) << 4);

    float o[8][4];
    #pragma unroll
    for (int i = 0; i < 8; i++)
        #pragma unroll
        for (int jx = 0; jx < 4; jx++) o[i][jx] = 0.0f;
    float lA = 0.0f, lB = 0.0f;

    // ---- prefetch tile 0 ----
    {
        uint32_t sb = sb0;
        #pragma unroll
        for (int i = 0; i < 2; i++) {
            uint32_t c = (uint32_t)tid * 16 + i * 4096;
            cp_async16(sb + c,        KH + c);
            cp_async16(sb + 8192 + c, VH + c);
        }
        if (tid < 16) cp_async16(sb + 16384 + tid * 16, MK + tid * 4);
        CP_COMMIT();
    }

    for (int kt = 0; kt < NT; kt++) {
        const int s = kt & 1;
        if (kt + 1 < NT) {
            uint32_t sb = sb0 + (s ^ 1) * STAGE_SZ;
            size_t toff = (size_t)(kt + 1) * 8192;
            #pragma unroll
            for (int i = 0; i < 2; i++) {
                uint32_t c = (uint32_t)tid * 16 + i * 4096;
                cp_async16(sb + c,        KH + toff + c);
                cp_async16(sb + 8192 + c, VH + toff + c);
            }
            if (tid < 16) cp_async16(sb + 16384 + tid * 16, MK + (kt + 1) * 64 + tid * 4);
            CP_COMMIT();
            CP_WAIT1();
        } else {
            CP_WAIT0();
        }
        __syncthreads();

        const uint32_t khiA = sb0 + s * STAGE_SZ;
        const uint32_t vhiA = khiA + 8192;
        const int* mjs = (const int*)(s_dyn + s * STAGE_SZ + 16384);

        #pragma unroll
        for (int half = 0; half < 2; half++) {
            float sf[4][4];
            #pragma unroll
            for (int i = 0; i < 4; i++)
                #pragma unroll
                for (int jx = 0; jx < 4; jx++) sf[i][jx] = 0.0f;

            #pragma unroll
            for (int nb2 = 0; nb2 < 2; nb2++) {
                #pragma unroll
                for (int kc = 0; kc < 4; kc++) {
                    uint32_t off = (uint32_t)((half * 2 + nb2) * 2048 + kc * 32) + lK;
                    uint32_t bh0, bh1, bh2, bh3;
                    ldsm_x4(bh0, bh1, bh2, bh3, (khiA + off) ^ xK);
                    mma16816(sf[2*nb2],   qhi[kc*4+0], qhi[kc*4+1], qhi[kc*4+2], qhi[kc*4+3], bh0, bh1);
                    mma16816(sf[2*nb2+1], qhi[kc*4+0], qhi[kc*4+1], qhi[kc*4+2], qhi[kc*4+3], bh2, bh3);
                }
            }

            uint32_t phi[8], plo[8];
            #pragma unroll
            for (int nb = 0; nb < 4; nb++) {
                int j0 = half * 32 + nb * 8 + cb;
                int mj0 = mjs[j0], mj1 = mjs[j0 + 1];
                float bA0 = mj0 ? bm1A : bm0A;
                float bA1 = mj1 ? bm1A : bm0A;
                float bB0 = mj0 ? bm1B : bm0B;
                float bB1 = mj1 ? bm1B : bm0B;
                float pA0 = __expf(fmaf(sf[nb][0], 0.125f, bA0));
                float pA1 = __expf(fmaf(sf[nb][1], 0.125f, bA1));
                float pB0 = __expf(fmaf(sf[nb][2], 0.125f, bB0));
                float pB1 = __expf(fmaf(sf[nb][3], 0.125f, bB1));
                lA += pA0 + pA1;
                lB += pB0 + pB1;
                phi[nb*2+0] = pack_h2(pA0, pA1);
                phi[nb*2+1] = pack_h2(pB0, pB1);
                plo[nb*2+0] = pack_h2(lo_res(pA0), lo_res(pA1));
                plo[nb*2+1] = pack_h2(lo_res(pB0), lo_res(pB1));
            }

            #pragma unroll
            for (int db2 = 0; db2 < 4; db2++) {
                #pragma unroll
                for (int kc = 0; kc < 2; kc++) {
                    uint32_t off = (uint32_t)((half * 2 + kc) * 2048 + db2 * 32) + lV;
                    uint32_t v0, v1, v2, v3;
                    ldsm_x4_t(v0, v1, v2, v3, (vhiA + off) ^ xV);
                    mma16816(o[2*db2],   phi[4*kc+0], phi[4*kc+1], phi[4*kc+2], phi[4*kc+3], v0, v1);
                    mma16816(o[2*db2+1], phi[4*kc+0], phi[4*kc+1], phi[4*kc+2], phi[4*kc+3], v2, v3);
                    mma16816(o[2*db2],   plo[4*kc+0], plo[4*kc+1], plo[4*kc+2], plo[4*kc+3], v0, v1);
                    mma16816(o[2*db2+1], plo[4*kc+0], plo[4*kc+1], plo[4*kc+2], plo[4*kc+3], v2, v3);
                }
            }
        }
        __syncthreads();
    }

    // ---- epilogue ----
    lA += __shfl_xor_sync(0xffffffffu, lA, 1);
    lA += __shfl_xor_sync(0xffffffffu, lA, 2);
    lB += __shfl_xor_sync(0xffffffffu, lB, 1);
    lB += __shfl_xor_sync(0xffffffffu, lB, 2);
    float iA = 1.0f / lA, iB = 1.0f / lB;

    float* yA = Yg + (size_t)rA * HD + cb;
    float* yB = yA + 8 * HD;
    #pragma unroll
    for (int db = 0; db < 8; db++) {
        *(float2*)(yA + db * 8) = make_float2(o[db][0] * iA, o[db][1] * iA);
        *(float2*)(yB + db * 8) = make_float2(o[db][2] * iB, o[db][3] * iB);
    }
}

// ---------------------------------------------------------------------------
extern "C" void kernel_launch(void* const* d_in, const int* in_sizes, int n_in,
                              void* d_out, int out_size)
{
    const float* x    = (const float*)d_in[0];
    const float* cosp = (const float*)d_in[1];
    const float* sinp = (const float*)d_in[2];
    const int*   tmsk = (const int*)  d_in[3];
    const float* Wq   = (const float*)d_in[4];
    const float* Wk   = (const float*)d_in[5];
    const float* Wv   = (const float*)d_in[6];
    const float* Wpr  = (const float*)d_in[7];
    const float* mbr  = (const float*)d_in[8];
    const int*   bsp  = (const int*)  d_in[9];
    float* out = (float*)d_out;

    cudaFuncSetAttribute(attn_kernel,
                         cudaFuncAttributeMaxDynamicSharedMemorySize, 2 * STAGE_SZ);

    dim3 gg(BATCH * SEQ / 128, NH);   // 64 x 6
    gemm_tc<0, 0, true,  1><<<gg, 256>>>(x, Wq, cosp, sinp, nullptr);
    gemm_tc<0, 1, true,  1><<<gg, 256>>>(x, Wk, cosp, sinp, nullptr);
    gemm_tc<0, 2, false, 3><<<gg, 256>>>(x, Wv, nullptr, nullptr, nullptr);

    attn_kernel<<<dim3(SEQ / 128, BATCH * NH), 256, 2 * STAGE_SZ>>>(tmsk, mbr, bsp);

    gemm_tc<1, 3, false, 3><<<gg, 256>>>(nullptr, Wpr, nullptr, nullptr, out);
}